// round 1
// baseline (speedup 1.0000x reference)
#include <cuda_runtime.h>
#include <cuda_bf16.h>
#include <cstdint>

// ---------------- model dims ----------------
#define BATCH 2
#define SEQ   2048
#define TOK   (BATCH*SEQ)        // 4096
#define HID   2048
#define NK    16
#define NV    32
#define DK    128
#define DV    128
#define KEYD  2048               // NK*DK
#define VALD  4096               // NV*DV
#define CONVD 8192               // 2*KEYD + VALD
#define PQKVZ 12288              // 2*KEYD + 2*VALD
#define EPSF  1e-6f

// ---------------- scratch (device globals; no allocation) ----------------
__device__ float g_qkvz [(size_t)TOK * PQKVZ];   // 201 MB
__device__ float g_ba   [(size_t)TOK * 64];
__device__ float g_conv [(size_t)TOK * CONVD];   // 134 MB (post conv+silu q|k|v)
__device__ float g_qn   [(size_t)TOK * KEYD];    // l2-normalized q
__device__ float g_kn   [(size_t)TOK * KEYD];    // l2-normalized k
__device__ float g_beta [(size_t)TOK * NV];
__device__ float g_gdec [(size_t)TOK * NV];      // exp(g)
__device__ float g_core [(size_t)TOK * VALD];    // 67 MB
__device__ float g_gated[(size_t)TOK * VALD];    // 67 MB

// ---------------- SGEMM (NT): C[m,n] = sum_k A[m*K+k]*B[n*K+k] ----------------
#define BM 128
#define BN 128
#define BKK 16
__global__ __launch_bounds__(256) void sgemm_nt(const float* __restrict__ A,
                                                const float* __restrict__ B,
                                                float* __restrict__ C,
                                                int M, int N, int K) {
    __shared__ float As[BKK][BM];
    __shared__ float Bs[BKK][BN];
    const int tid = threadIdx.x;
    const int bm = blockIdx.y * BM;
    const int bn = blockIdx.x * BN;
    const int tx = tid & 15;          // 0..15 -> 8 cols each
    const int ty = tid >> 4;          // 0..15 -> 8 rows each
    const int lrow = tid >> 2;        // 0..63
    const int lk4  = (tid & 3) * 4;   // 0,4,8,12

    float acc[8][8];
    #pragma unroll
    for (int i = 0; i < 8; i++)
        #pragma unroll
        for (int j = 0; j < 8; j++) acc[i][j] = 0.f;

    for (int k0 = 0; k0 < K; k0 += BKK) {
        #pragma unroll
        for (int it = 0; it < 2; it++) {
            int row = lrow + it * 64;
            float4 v = *(const float4*)(A + (size_t)(bm + row) * K + k0 + lk4);
            As[lk4+0][row] = v.x; As[lk4+1][row] = v.y;
            As[lk4+2][row] = v.z; As[lk4+3][row] = v.w;
        }
        #pragma unroll
        for (int it = 0; it < 2; it++) {
            int row = lrow + it * 64;
            int gn = bn + row;
            float4 v = make_float4(0.f,0.f,0.f,0.f);
            if (gn < N) v = *(const float4*)(B + (size_t)gn * K + k0 + lk4);
            Bs[lk4+0][row] = v.x; Bs[lk4+1][row] = v.y;
            Bs[lk4+2][row] = v.z; Bs[lk4+3][row] = v.w;
        }
        __syncthreads();
        #pragma unroll
        for (int kk = 0; kk < BKK; kk++) {
            float ar[8], br[8];
            #pragma unroll
            for (int i = 0; i < 8; i++) ar[i] = As[kk][ty*8 + i];
            #pragma unroll
            for (int j = 0; j < 8; j++) br[j] = Bs[kk][tx*8 + j];
            #pragma unroll
            for (int i = 0; i < 8; i++)
                #pragma unroll
                for (int j = 0; j < 8; j++)
                    acc[i][j] = fmaf(ar[i], br[j], acc[i][j]);
        }
        __syncthreads();
    }
    #pragma unroll
    for (int i = 0; i < 8; i++) {
        int gm = bm + ty*8 + i;
        #pragma unroll
        for (int j = 0; j < 8; j++) {
            int gn = bn + tx*8 + j;
            if (gn < N) C[(size_t)gm * N + gn] = acc[i][j];
        }
    }
}

// ---------------- depthwise causal conv1d (K=4) + SiLU ----------------
// in  = g_qkvz[:, 0:8192] layout [T, 12288]; out = g_conv layout [T, 8192]
__global__ void conv_silu_kernel(const float* __restrict__ qkvz,
                                 const float* __restrict__ cw,
                                 float* __restrict__ out) {
    size_t idx = (size_t)blockIdx.x * blockDim.x + threadIdx.x;
    int c = (int)(idx & (CONVD - 1));
    size_t t = idx >> 13;                 // CONVD = 2^13
    int s = (int)(t & (SEQ - 1));
    size_t b = t >> 11;                   // SEQ = 2^11
    const float* base = qkvz + (b * SEQ) * (size_t)PQKVZ + c;
    float w0 = cw[c*4+0], w1 = cw[c*4+1], w2 = cw[c*4+2], w3 = cw[c*4+3];
    float acc = w3 * base[(size_t)s * PQKVZ];
    if (s >= 1) acc = fmaf(w2, base[(size_t)(s-1) * PQKVZ], acc);
    if (s >= 2) acc = fmaf(w1, base[(size_t)(s-2) * PQKVZ], acc);
    if (s >= 3) acc = fmaf(w0, base[(size_t)(s-3) * PQKVZ], acc);
    out[idx] = acc / (1.f + expf(-acc));  // silu
}

// ---------------- l2norm(q,k) per NK head + beta/g gates ----------------
__global__ __launch_bounds__(512) void prep_kernel(const float* __restrict__ conv,
                                                   const float* __restrict__ ba,
                                                   const float* __restrict__ dt_bias,
                                                   const float* __restrict__ A_log,
                                                   float* __restrict__ qn,
                                                   float* __restrict__ kn,
                                                   float* __restrict__ beta,
                                                   float* __restrict__ gdec) {
    size_t t = blockIdx.x;
    int w = threadIdx.x >> 5;   // head 0..15
    int l = threadIdx.x & 31;
    const float* cq = conv + t * CONVD + w * DK;
    const float* ck = conv + t * CONVD + KEYD + w * DK;
    float qv[4], kv[4];
    float sq = 0.f, sk = 0.f;
    #pragma unroll
    for (int i = 0; i < 4; i++) {
        qv[i] = cq[l + 32*i]; sq = fmaf(qv[i], qv[i], sq);
        kv[i] = ck[l + 32*i]; sk = fmaf(kv[i], kv[i], sk);
    }
    #pragma unroll
    for (int o = 16; o; o >>= 1) {
        sq += __shfl_xor_sync(0xffffffffu, sq, o);
        sk += __shfl_xor_sync(0xffffffffu, sk, o);
    }
    float rq = rsqrtf(sq + EPSF), rk = rsqrtf(sk + EPSF);
    #pragma unroll
    for (int i = 0; i < 4; i++) {
        qn[(t*NK + w)*DK + l + 32*i] = qv[i] * rq;
        kn[(t*NK + w)*DK + l + 32*i] = kv[i] * rk;
    }
    if (threadIdx.x < NV) {
        int h = threadIdx.x;
        float bv = ba[t*64 + h];
        float av = ba[t*64 + NV + h];
        beta[t*NV + h] = 1.f / (1.f + expf(-bv));
        float x = av + dt_bias[h];
        float sp = (x > 20.f) ? x : log1pf(expf(x));
        gdec[t*NV + h] = expf(-expf(A_log[h]) * sp);
    }
}

// ---------------- sequential gated delta-rule scan ----------------
// grid (NV, B); 128 threads; thread = one DV column; state[128] in registers.
__global__ __launch_bounds__(128) void scan_kernel(const float* __restrict__ qn,
                                                   const float* __restrict__ kn,
                                                   const float* __restrict__ conv,
                                                   const float* __restrict__ beta,
                                                   const float* __restrict__ gdec,
                                                   float* __restrict__ core) {
    const int h  = blockIdx.x;      // 0..31 value head
    const int b  = blockIdx.y;
    const int nk = h >> 1;          // rep = NV/NK = 2
    const int tid = threadIdx.x;    // dv column
    __shared__ float4 ks4[32], qs4[32];
    float st[128];
    #pragma unroll
    for (int j = 0; j < 128; j++) st[j] = 0.f;

    for (int s = 0; s < SEQ; s++) {
        size_t t = (size_t)b * SEQ + s;
        __syncthreads();
        if (tid < 32)
            ks4[tid] = *(const float4*)(kn + (t*NK + nk)*DK + tid*4);
        else if (tid < 64)
            qs4[tid-32] = *(const float4*)(qn + (t*NK + nk)*DK + (tid-32)*4);
        float vt = conv[t*CONVD + KEYD*2 + h*DV + tid];
        float ge = gdec[t*NV + h];
        float bt = beta[t*NV + h];
        __syncthreads();

        float kvd = 0.f;
        #pragma unroll
        for (int j = 0; j < 32; j++) {
            float4 k4 = ks4[j];
            kvd = fmaf(k4.x, st[4*j+0], kvd);
            kvd = fmaf(k4.y, st[4*j+1], kvd);
            kvd = fmaf(k4.z, st[4*j+2], kvd);
            kvd = fmaf(k4.w, st[4*j+3], kvd);
        }
        float delta = bt * (vt - ge * kvd);
        float o = 0.f;
        #pragma unroll
        for (int j = 0; j < 32; j++) {
            float4 k4 = ks4[j];
            float4 q4 = qs4[j];
            st[4*j+0] = fmaf(ge, st[4*j+0], k4.x * delta);
            o = fmaf(q4.x, st[4*j+0], o);
            st[4*j+1] = fmaf(ge, st[4*j+1], k4.y * delta);
            o = fmaf(q4.y, st[4*j+1], o);
            st[4*j+2] = fmaf(ge, st[4*j+2], k4.z * delta);
            o = fmaf(q4.z, st[4*j+2], o);
            st[4*j+3] = fmaf(ge, st[4*j+3], k4.w * delta);
            o = fmaf(q4.w, st[4*j+3], o);
        }
        core[t*VALD + h*DV + tid] = o;
    }
}

// ---------------- RMSNorm(1+w) + silu(z) gate ----------------
__global__ __launch_bounds__(256) void rmsnorm_gate_kernel(const float* __restrict__ core,
                                                           const float* __restrict__ qkvz,
                                                           const float* __restrict__ norm_w,
                                                           float* __restrict__ gated) {
    size_t t = blockIdx.x;
    __shared__ float red[8];
    __shared__ float s_scale;
    const float* row = core + t * VALD;
    const float* zrow = qkvz + t * PQKVZ + 2*KEYD + VALD;  // z offset 8192
    float ss = 0.f;
    for (int c = threadIdx.x; c < VALD; c += 256) { float v = row[c]; ss = fmaf(v, v, ss); }
    #pragma unroll
    for (int o = 16; o; o >>= 1) ss += __shfl_xor_sync(0xffffffffu, ss, o);
    if ((threadIdx.x & 31) == 0) red[threadIdx.x >> 5] = ss;
    __syncthreads();
    if (threadIdx.x == 0) {
        float tot = 0.f;
        #pragma unroll
        for (int i = 0; i < 8; i++) tot += red[i];
        s_scale = rsqrtf(tot * (1.f / VALD) + EPSF);
    }
    __syncthreads();
    float sc = s_scale;
    for (int c = threadIdx.x; c < VALD; c += 256) {
        float z = zrow[c];
        float sz = z / (1.f + expf(-z));
        gated[t*VALD + c] = row[c] * sc * (1.f + norm_w[c]) * sz;
    }
}

// ---------------- launch ----------------
extern "C" void kernel_launch(void* const* d_in, const int* in_sizes, int n_in,
                              void* d_out, int out_size) {
    const float* x       = (const float*)d_in[0];
    const float* W_qkvz  = (const float*)d_in[1];
    const float* W_ba    = (const float*)d_in[2];
    const float* conv_w  = (const float*)d_in[3];
    const float* dt_bias = (const float*)d_in[4];
    const float* A_log   = (const float*)d_in[5];
    const float* norm_w  = (const float*)d_in[6];
    const float* W_out   = (const float*)d_in[7];
    float* out = (float*)d_out;

    float *p_qkvz, *p_ba, *p_conv, *p_qn, *p_kn, *p_beta, *p_g, *p_core, *p_gated;
    cudaGetSymbolAddress((void**)&p_qkvz,  g_qkvz);
    cudaGetSymbolAddress((void**)&p_ba,    g_ba);
    cudaGetSymbolAddress((void**)&p_conv,  g_conv);
    cudaGetSymbolAddress((void**)&p_qn,    g_qn);
    cudaGetSymbolAddress((void**)&p_kn,    g_kn);
    cudaGetSymbolAddress((void**)&p_beta,  g_beta);
    cudaGetSymbolAddress((void**)&p_g,     g_gdec);
    cudaGetSymbolAddress((void**)&p_core,  g_core);
    cudaGetSymbolAddress((void**)&p_gated, g_gated);

    // 1) qkvz = x @ W_qkvz^T   [4096 x 12288]
    sgemm_nt<<<dim3(PQKVZ/BN, TOK/BM), 256>>>(x, W_qkvz, p_qkvz, TOK, PQKVZ, HID);
    // 2) ba = x @ W_ba^T       [4096 x 64]
    sgemm_nt<<<dim3(1, TOK/BM), 256>>>(x, W_ba, p_ba, TOK, 64, HID);
    // 3) depthwise conv + silu
    conv_silu_kernel<<<(TOK*(size_t)CONVD)/256, 256>>>(p_qkvz, conv_w, p_conv);
    // 4) l2norm + gates
    prep_kernel<<<TOK, 512>>>(p_conv, p_ba, dt_bias, A_log, p_qn, p_kn, p_beta, p_g);
    // 5) delta-rule scan
    scan_kernel<<<dim3(NV, BATCH), 128>>>(p_qn, p_kn, p_conv, p_beta, p_g, p_core);
    // 6) rmsnorm + gate
    rmsnorm_gate_kernel<<<TOK, 256>>>(p_core, p_qkvz, norm_w, p_gated);
    // 7) out = gated @ W_out^T [4096 x 2048]
    sgemm_nt<<<dim3(HID/BN, TOK/BM), 256>>>(p_gated, W_out, out, TOK, HID, VALD);
}

// round 3
// speedup vs baseline: 2.3541x; 2.3541x over previous
#include <cuda_runtime.h>
#include <cuda_bf16.h>
#include <cstdint>

// ---------------- model dims ----------------
#define BATCH 2
#define SEQ   2048
#define TOK   (BATCH*SEQ)        // 4096
#define HID   2048
#define NK    16
#define NV    32
#define DK    128
#define DV    128
#define KEYD  2048               // NK*DK
#define VALD  4096               // NV*DV
#define CONVD 8192               // 2*KEYD + VALD
#define PQKVZ 12288              // 2*KEYD + 2*VALD
#define EPSF  1e-6f

// ---------------- scratch (device globals; no allocation) ----------------
__device__ float g_qkvz [(size_t)TOK * PQKVZ];
__device__ float g_ba   [(size_t)TOK * 64];
__device__ float g_conv [(size_t)TOK * CONVD];
__device__ float g_qn   [(size_t)TOK * KEYD];
__device__ float g_kn   [(size_t)TOK * KEYD];
__device__ float g_beta [(size_t)TOK * NV];
__device__ float g_gdec [(size_t)TOK * NV];
__device__ float g_core [(size_t)TOK * VALD];
__device__ float g_gated[(size_t)TOK * VALD];
// bf16 hi/lo split scratch
__device__ __nv_bfloat16 g_xhi [(size_t)TOK * HID];
__device__ __nv_bfloat16 g_xlo [(size_t)TOK * HID];
__device__ __nv_bfloat16 g_w1hi[(size_t)PQKVZ * HID];
__device__ __nv_bfloat16 g_w1lo[(size_t)PQKVZ * HID];
__device__ __nv_bfloat16 g_w2hi[(size_t)HID * VALD];
__device__ __nv_bfloat16 g_w2lo[(size_t)HID * VALD];
__device__ __nv_bfloat16 g_ghi [(size_t)TOK * VALD];
__device__ __nv_bfloat16 g_glo [(size_t)TOK * VALD];

// ---------------- helpers ----------------
__device__ __forceinline__ uint32_t smem_u32(const void* p) {
    uint32_t r;
    asm("{ .reg .u64 t; cvta.to.shared.u64 t, %1; cvt.u32.u64 %0, t; }" : "=r"(r) : "l"(p));
    return r;
}
__device__ __forceinline__ void cpasync16(uint32_t s, const void* g) {
    asm volatile("cp.async.cg.shared.global [%0], [%1], 16;" :: "r"(s), "l"(g));
}
__device__ __forceinline__ uint32_t lds32(uint32_t a) {
    uint32_t v; asm volatile("ld.shared.b32 %0, [%1];" : "=r"(v) : "r"(a)); return v;
}
__device__ __forceinline__ void mma16816(float* c, const uint32_t* a, const uint32_t* b) {
    asm volatile(
        "mma.sync.aligned.m16n8k16.row.col.f32.bf16.bf16.f32 "
        "{%0,%1,%2,%3}, {%4,%5,%6,%7}, {%8,%9}, {%0,%1,%2,%3};"
        : "+f"(c[0]), "+f"(c[1]), "+f"(c[2]), "+f"(c[3])
        : "r"(a[0]), "r"(a[1]), "r"(a[2]), "r"(a[3]), "r"(b[0]), "r"(b[1]));
}

// ---------------- split fp32 -> bf16 hi/lo ----------------
__global__ __launch_bounds__(256) void split_bf16(const float* __restrict__ src,
                                                  __nv_bfloat16* __restrict__ hi,
                                                  __nv_bfloat16* __restrict__ lo) {
    size_t i = ((size_t)blockIdx.x * blockDim.x + threadIdx.x) * 4;
    float4 v = *(const float4*)(src + i);
    __nv_bfloat16 h0 = __float2bfloat16(v.x), h1 = __float2bfloat16(v.y);
    __nv_bfloat16 h2 = __float2bfloat16(v.z), h3 = __float2bfloat16(v.w);
    __nv_bfloat16 l0 = __float2bfloat16(v.x - __bfloat162float(h0));
    __nv_bfloat16 l1 = __float2bfloat16(v.y - __bfloat162float(h1));
    __nv_bfloat16 l2 = __float2bfloat16(v.z - __bfloat162float(h2));
    __nv_bfloat16 l3 = __float2bfloat16(v.w - __bfloat162float(h3));
    __nv_bfloat162* hp = (__nv_bfloat162*)(hi + i);
    __nv_bfloat162* lp = (__nv_bfloat162*)(lo + i);
    hp[0] = __nv_bfloat162(h0, h1); hp[1] = __nv_bfloat162(h2, h3);
    lp[0] = __nv_bfloat162(l0, l1); lp[1] = __nv_bfloat162(l2, l3);
}

// ---------------- mma.sync bf16x3 GEMM (NT): C[m,n] = sum_k A[m,k]*B[n,k] ----------------
// CTA 128x128, K-stage 32, 256 threads (8 warps: 2(M) x 4(N), warp tile 64x32).
// Smem tiles padded to 80B rows (conflict-free fragment LDS + 16B cp.async alignment).
#define TSTRIDE 80
#define TILE_B  (128 * TSTRIDE)     // 10240
#define STAGE_B (4 * TILE_B)        // 40960: Ah | Al | Bh | Bl
#define GSMEM   (2 * STAGE_B)       // 81920

__global__ __launch_bounds__(256)
void gemm_bf16x3(const __nv_bfloat16* __restrict__ Ah, const __nv_bfloat16* __restrict__ Al,
                 const __nv_bfloat16* __restrict__ Bh, const __nv_bfloat16* __restrict__ Bl,
                 float* __restrict__ C, int M, int N, int K) {
    extern __shared__ char sm[];
    const uint32_t sb = smem_u32(sm);
    const int tid = threadIdx.x;
    const int lane = tid & 31, wid = tid >> 5;
    const int bm = blockIdx.x * 128, bn = blockIdx.y * 128;
    const int wm = (wid & 1) * 64, wn = (wid >> 1) * 32;
    const int grp = lane >> 2, qid = lane & 3;

    float c[4][4][4];
    #pragma unroll
    for (int i = 0; i < 4; i++)
        #pragma unroll
        for (int j = 0; j < 4; j++)
            #pragma unroll
            for (int r = 0; r < 4; r++) c[i][j][r] = 0.f;

    const int niter = K >> 5;   // K/32

    // async copy one k-stage into buffer `buf`
    auto issue = [&](int kblk, int buf) {
        const int k0 = kblk * 32;
        #pragma unroll
        for (int i = 0; i < 2; i++) {
            int chunk = tid + i * 256;
            int row = chunk >> 2, c16 = chunk & 3;
            size_t ga = (size_t)(bm + row) * K + k0 + c16 * 8;
            size_t gb = (size_t)(bn + row) * K + k0 + c16 * 8;
            uint32_t so = sb + buf * STAGE_B + row * TSTRIDE + c16 * 16;
            cpasync16(so,              Ah + ga);
            cpasync16(so + TILE_B,     Al + ga);
            cpasync16(so + 2 * TILE_B, Bh + gb);
            cpasync16(so + 3 * TILE_B, Bl + gb);
        }
    };

    issue(0, 0);
    asm volatile("cp.async.commit_group;" ::: "memory");
    issue(1, 1);
    asm volatile("cp.async.commit_group;" ::: "memory");

    for (int it = 0; it < niter; it++) {
        asm volatile("cp.async.wait_group 1;" ::: "memory");
        __syncthreads();
        const int buf = it & 1;
        const uint32_t base = sb + buf * STAGE_B;

        #pragma unroll
        for (int ks = 0; ks < 2; ks++) {
            const uint32_t koff = ks * 32;   // 16 halves
            uint32_t ah[4][4], al[4][4], bh[4][2], bl[4][2];
            #pragma unroll
            for (int i = 0; i < 4; i++) {
                uint32_t r0 = base + (uint32_t)(wm + i * 16 + grp) * TSTRIDE + qid * 4 + koff;
                ah[i][0] = lds32(r0);
                ah[i][1] = lds32(r0 + 8 * TSTRIDE);
                ah[i][2] = lds32(r0 + 16);
                ah[i][3] = lds32(r0 + 8 * TSTRIDE + 16);
                al[i][0] = lds32(r0 + TILE_B);
                al[i][1] = lds32(r0 + TILE_B + 8 * TSTRIDE);
                al[i][2] = lds32(r0 + TILE_B + 16);
                al[i][3] = lds32(r0 + TILE_B + 8 * TSTRIDE + 16);
            }
            #pragma unroll
            for (int j = 0; j < 4; j++) {
                uint32_t rb = base + 2 * TILE_B + (uint32_t)(wn + j * 8 + grp) * TSTRIDE + qid * 4 + koff;
                bh[j][0] = lds32(rb);
                bh[j][1] = lds32(rb + 16);
                bl[j][0] = lds32(rb + TILE_B);
                bl[j][1] = lds32(rb + TILE_B + 16);
            }
            #pragma unroll
            for (int i = 0; i < 4; i++)
                #pragma unroll
                for (int j = 0; j < 4; j++) {
                    mma16816(c[i][j], ah[i], bh[j]);
                    mma16816(c[i][j], al[i], bh[j]);
                    mma16816(c[i][j], ah[i], bl[j]);
                }
        }
        __syncthreads();
        if (it + 2 < niter) issue(it + 2, buf);
        asm volatile("cp.async.commit_group;" ::: "memory");
    }

    #pragma unroll
    for (int i = 0; i < 4; i++) {
        const int row0 = bm + wm + i * 16 + grp;
        #pragma unroll
        for (int j = 0; j < 4; j++) {
            const int col = bn + wn + j * 8 + qid * 2;
            float2 v01 = make_float2(c[i][j][0], c[i][j][1]);
            float2 v23 = make_float2(c[i][j][2], c[i][j][3]);
            *(float2*)(C + (size_t)row0 * N + col)       = v01;
            *(float2*)(C + (size_t)(row0 + 8) * N + col) = v23;
        }
    }
}

// ---------------- SIMT SGEMM (NT) for tiny ba GEMM ----------------
#define BM 128
#define BN 128
#define BKK 16
__global__ __launch_bounds__(256) void sgemm_nt(const float* __restrict__ A,
                                                const float* __restrict__ B,
                                                float* __restrict__ C,
                                                int M, int N, int K) {
    __shared__ float As[BKK][BM];
    __shared__ float Bs[BKK][BN];
    const int tid = threadIdx.x;
    const int bm = blockIdx.y * BM;
    const int bn = blockIdx.x * BN;
    const int tx = tid & 15;
    const int ty = tid >> 4;
    const int lrow = tid >> 2;
    const int lk4 = (tid & 3) * 4;

    float acc[8][8];
    #pragma unroll
    for (int i = 0; i < 8; i++)
        #pragma unroll
        for (int j = 0; j < 8; j++) acc[i][j] = 0.f;

    for (int k0 = 0; k0 < K; k0 += BKK) {
        #pragma unroll
        for (int it = 0; it < 2; it++) {
            int row = lrow + it * 64;
            float4 v = *(const float4*)(A + (size_t)(bm + row) * K + k0 + lk4);
            As[lk4 + 0][row] = v.x; As[lk4 + 1][row] = v.y;
            As[lk4 + 2][row] = v.z; As[lk4 + 3][row] = v.w;
        }
        #pragma unroll
        for (int it = 0; it < 2; it++) {
            int row = lrow + it * 64;
            int gn = bn + row;
            float4 v = make_float4(0.f, 0.f, 0.f, 0.f);
            if (gn < N) v = *(const float4*)(B + (size_t)gn * K + k0 + lk4);
            Bs[lk4 + 0][row] = v.x; Bs[lk4 + 1][row] = v.y;
            Bs[lk4 + 2][row] = v.z; Bs[lk4 + 3][row] = v.w;
        }
        __syncthreads();
        #pragma unroll
        for (int kk = 0; kk < BKK; kk++) {
            float ar[8], br[8];
            #pragma unroll
            for (int i = 0; i < 8; i++) ar[i] = As[kk][ty * 8 + i];
            #pragma unroll
            for (int j = 0; j < 8; j++) br[j] = Bs[kk][tx * 8 + j];
            #pragma unroll
            for (int i = 0; i < 8; i++)
                #pragma unroll
                for (int j = 0; j < 8; j++)
                    acc[i][j] = fmaf(ar[i], br[j], acc[i][j]);
        }
        __syncthreads();
    }
    #pragma unroll
    for (int i = 0; i < 8; i++) {
        int gm = bm + ty * 8 + i;
        #pragma unroll
        for (int j = 0; j < 8; j++) {
            int gn = bn + tx * 8 + j;
            if (gn < N) C[(size_t)gm * N + gn] = acc[i][j];
        }
    }
}

// ---------------- depthwise causal conv1d (K=4) + SiLU ----------------
__global__ void conv_silu_kernel(const float* __restrict__ qkvz,
                                 const float* __restrict__ cw,
                                 float* __restrict__ out) {
    size_t idx = (size_t)blockIdx.x * blockDim.x + threadIdx.x;
    int c = (int)(idx & (CONVD - 1));
    size_t t = idx >> 13;
    int s = (int)(t & (SEQ - 1));
    size_t b = t >> 11;
    const float* base = qkvz + (b * SEQ) * (size_t)PQKVZ + c;
    float w0 = cw[c * 4 + 0], w1 = cw[c * 4 + 1], w2 = cw[c * 4 + 2], w3 = cw[c * 4 + 3];
    float acc = w3 * base[(size_t)s * PQKVZ];
    if (s >= 1) acc = fmaf(w2, base[(size_t)(s - 1) * PQKVZ], acc);
    if (s >= 2) acc = fmaf(w1, base[(size_t)(s - 2) * PQKVZ], acc);
    if (s >= 3) acc = fmaf(w0, base[(size_t)(s - 3) * PQKVZ], acc);
    out[idx] = acc / (1.f + expf(-acc));
}

// ---------------- l2norm(q,k) + gates ----------------
__global__ __launch_bounds__(512) void prep_kernel(const float* __restrict__ conv,
                                                   const float* __restrict__ ba,
                                                   const float* __restrict__ dt_bias,
                                                   const float* __restrict__ A_log,
                                                   float* __restrict__ qn,
                                                   float* __restrict__ kn,
                                                   float* __restrict__ beta,
                                                   float* __restrict__ gdec) {
    size_t t = blockIdx.x;
    int w = threadIdx.x >> 5;
    int l = threadIdx.x & 31;
    const float* cq = conv + t * CONVD + w * DK;
    const float* ck = conv + t * CONVD + KEYD + w * DK;
    float qv[4], kv[4];
    float sq = 0.f, sk = 0.f;
    #pragma unroll
    for (int i = 0; i < 4; i++) {
        qv[i] = cq[l + 32 * i]; sq = fmaf(qv[i], qv[i], sq);
        kv[i] = ck[l + 32 * i]; sk = fmaf(kv[i], kv[i], sk);
    }
    #pragma unroll
    for (int o = 16; o; o >>= 1) {
        sq += __shfl_xor_sync(0xffffffffu, sq, o);
        sk += __shfl_xor_sync(0xffffffffu, sk, o);
    }
    float rq = rsqrtf(sq + EPSF), rk = rsqrtf(sk + EPSF);
    #pragma unroll
    for (int i = 0; i < 4; i++) {
        qn[(t * NK + w) * DK + l + 32 * i] = qv[i] * rq;
        kn[(t * NK + w) * DK + l + 32 * i] = kv[i] * rk;
    }
    if (threadIdx.x < NV) {
        int h = threadIdx.x;
        float bv = ba[t * 64 + h];
        float av = ba[t * 64 + NV + h];
        beta[t * NV + h] = 1.f / (1.f + expf(-bv));
        float xx = av + dt_bias[h];
        float sp = (xx > 20.f) ? xx : log1pf(expf(xx));
        gdec[t * NV + h] = expf(-expf(A_log[h]) * sp);
    }
}

// ---------------- sequential gated delta-rule scan ----------------
__global__ __launch_bounds__(128) void scan_kernel(const float* __restrict__ qn,
                                                   const float* __restrict__ kn,
                                                   const float* __restrict__ conv,
                                                   const float* __restrict__ beta,
                                                   const float* __restrict__ gdec,
                                                   float* __restrict__ core) {
    const int h = blockIdx.x;
    const int b = blockIdx.y;
    const int nk = h >> 1;
    const int tid = threadIdx.x;
    __shared__ float4 ks4[32], qs4[32];
    float st[128];
    #pragma unroll
    for (int j = 0; j < 128; j++) st[j] = 0.f;

    for (int s = 0; s < SEQ; s++) {
        size_t t = (size_t)b * SEQ + s;
        __syncthreads();
        if (tid < 32)
            ks4[tid] = *(const float4*)(kn + (t * NK + nk) * DK + tid * 4);
        else if (tid < 64)
            qs4[tid - 32] = *(const float4*)(qn + (t * NK + nk) * DK + (tid - 32) * 4);
        float vt = conv[t * CONVD + KEYD * 2 + h * DV + tid];
        float ge = gdec[t * NV + h];
        float bt = beta[t * NV + h];
        __syncthreads();

        float kvd = 0.f;
        #pragma unroll
        for (int j = 0; j < 32; j++) {
            float4 k4 = ks4[j];
            kvd = fmaf(k4.x, st[4 * j + 0], kvd);
            kvd = fmaf(k4.y, st[4 * j + 1], kvd);
            kvd = fmaf(k4.z, st[4 * j + 2], kvd);
            kvd = fmaf(k4.w, st[4 * j + 3], kvd);
        }
        float delta = bt * (vt - ge * kvd);
        float o = 0.f;
        #pragma unroll
        for (int j = 0; j < 32; j++) {
            float4 k4 = ks4[j];
            float4 q4 = qs4[j];
            st[4 * j + 0] = fmaf(ge, st[4 * j + 0], k4.x * delta);
            o = fmaf(q4.x, st[4 * j + 0], o);
            st[4 * j + 1] = fmaf(ge, st[4 * j + 1], k4.y * delta);
            o = fmaf(q4.y, st[4 * j + 1], o);
            st[4 * j + 2] = fmaf(ge, st[4 * j + 2], k4.z * delta);
            o = fmaf(q4.z, st[4 * j + 2], o);
            st[4 * j + 3] = fmaf(ge, st[4 * j + 3], k4.w * delta);
            o = fmaf(q4.w, st[4 * j + 3], o);
        }
        core[t * VALD + h * DV + tid] = o;
    }
}

// ---------------- RMSNorm(1+w) + silu(z) gate ----------------
__global__ __launch_bounds__(256) void rmsnorm_gate_kernel(const float* __restrict__ core,
                                                           const float* __restrict__ qkvz,
                                                           const float* __restrict__ norm_w,
                                                           float* __restrict__ gated) {
    size_t t = blockIdx.x;
    __shared__ float red[8];
    __shared__ float s_scale;
    const float* row = core + t * VALD;
    const float* zrow = qkvz + t * PQKVZ + 2 * KEYD + VALD;
    float ss = 0.f;
    for (int c = threadIdx.x; c < VALD; c += 256) { float v = row[c]; ss = fmaf(v, v, ss); }
    #pragma unroll
    for (int o = 16; o; o >>= 1) ss += __shfl_xor_sync(0xffffffffu, ss, o);
    if ((threadIdx.x & 31) == 0) red[threadIdx.x >> 5] = ss;
    __syncthreads();
    if (threadIdx.x == 0) {
        float tot = 0.f;
        #pragma unroll
        for (int i = 0; i < 8; i++) tot += red[i];
        s_scale = rsqrtf(tot * (1.f / VALD) + EPSF);
    }
    __syncthreads();
    float sc = s_scale;
    for (int c = threadIdx.x; c < VALD; c += 256) {
        float z = zrow[c];
        float sz = z / (1.f + expf(-z));
        gated[t * VALD + c] = row[c] * sc * (1.f + norm_w[c]) * sz;
    }
}

// ---------------- launch ----------------
extern "C" void kernel_launch(void* const* d_in, const int* in_sizes, int n_in,
                              void* d_out, int out_size) {
    const float* x       = (const float*)d_in[0];
    const float* W_qkvz  = (const float*)d_in[1];
    const float* W_ba    = (const float*)d_in[2];
    const float* conv_w  = (const float*)d_in[3];
    const float* dt_bias = (const float*)d_in[4];
    const float* A_log   = (const float*)d_in[5];
    const float* norm_w  = (const float*)d_in[6];
    const float* W_out   = (const float*)d_in[7];
    float* out = (float*)d_out;

    float *p_qkvz, *p_ba, *p_conv, *p_qn, *p_kn, *p_beta, *p_g, *p_core, *p_gated;
    __nv_bfloat16 *p_xhi, *p_xlo, *p_w1hi, *p_w1lo, *p_w2hi, *p_w2lo, *p_ghi, *p_glo;
    cudaGetSymbolAddress((void**)&p_qkvz,  g_qkvz);
    cudaGetSymbolAddress((void**)&p_ba,    g_ba);
    cudaGetSymbolAddress((void**)&p_conv,  g_conv);
    cudaGetSymbolAddress((void**)&p_qn,    g_qn);
    cudaGetSymbolAddress((void**)&p_kn,    g_kn);
    cudaGetSymbolAddress((void**)&p_beta,  g_beta);
    cudaGetSymbolAddress((void**)&p_g,     g_gdec);
    cudaGetSymbolAddress((void**)&p_core,  g_core);
    cudaGetSymbolAddress((void**)&p_gated, g_gated);
    cudaGetSymbolAddress((void**)&p_xhi,  g_xhi);
    cudaGetSymbolAddress((void**)&p_xlo,  g_xlo);
    cudaGetSymbolAddress((void**)&p_w1hi, g_w1hi);
    cudaGetSymbolAddress((void**)&p_w1lo, g_w1lo);
    cudaGetSymbolAddress((void**)&p_w2hi, g_w2hi);
    cudaGetSymbolAddress((void**)&p_w2lo, g_w2lo);
    cudaGetSymbolAddress((void**)&p_ghi,  g_ghi);
    cudaGetSymbolAddress((void**)&p_glo,  g_glo);

    cudaFuncSetAttribute(gemm_bf16x3, cudaFuncAttributeMaxDynamicSharedMemorySize, GSMEM);

    // splits for GEMM operands
    split_bf16<<<(TOK * (size_t)HID) / 1024, 256>>>(x, p_xhi, p_xlo);
    split_bf16<<<((size_t)PQKVZ * HID) / 1024, 256>>>(W_qkvz, p_w1hi, p_w1lo);
    split_bf16<<<((size_t)HID * VALD) / 1024, 256>>>(W_out, p_w2hi, p_w2lo);

    // 1) qkvz = x @ W_qkvz^T  (mma.sync bf16x3)
    gemm_bf16x3<<<dim3(TOK / 128, PQKVZ / 128), 256, GSMEM>>>(
        p_xhi, p_xlo, p_w1hi, p_w1lo, p_qkvz, TOK, PQKVZ, HID);
    // 2) ba = x @ W_ba^T (SIMT, tiny)
    sgemm_nt<<<dim3(1, TOK / BM), 256>>>(x, W_ba, p_ba, TOK, 64, HID);
    // 3) conv + silu
    conv_silu_kernel<<<(TOK * (size_t)CONVD) / 256, 256>>>(p_qkvz, conv_w, p_conv);
    // 4) l2norm + gates
    prep_kernel<<<TOK, 512>>>(p_conv, p_ba, dt_bias, A_log, p_qn, p_kn, p_beta, p_g);
    // 5) delta-rule scan
    scan_kernel<<<dim3(NV, BATCH), 128>>>(p_qn, p_kn, p_conv, p_beta, p_g, p_core);
    // 6) rmsnorm + gate
    rmsnorm_gate_kernel<<<TOK, 256>>>(p_core, p_qkvz, norm_w, p_gated);
    // 7) split gated, then out = gated @ W_out^T (mma.sync bf16x3)
    split_bf16<<<(TOK * (size_t)VALD) / 1024, 256>>>(p_gated, p_ghi, p_glo);
    gemm_bf16x3<<<dim3(TOK / 128, HID / 128), 256, GSMEM>>>(
        p_ghi, p_glo, p_w2hi, p_w2lo, out, TOK, HID, VALD);
}

// round 4
// speedup vs baseline: 2.5798x; 1.0959x over previous
#include <cuda_runtime.h>
#include <cuda_bf16.h>
#include <cstdint>

// ---------------- model dims ----------------
#define BATCH 2
#define SEQ   2048
#define TOK   (BATCH*SEQ)        // 4096
#define HID   2048
#define NK    16
#define NV    32
#define DK    128
#define DV    128
#define KEYD  2048               // NK*DK
#define VALD  4096               // NV*DV
#define CONVD 8192               // 2*KEYD + VALD
#define PQKVZ 12288              // 2*KEYD + 2*VALD
#define EPSF  1e-6f

// ---------------- scratch (device globals; no allocation) ----------------
__device__ float g_qkvz [(size_t)TOK * PQKVZ];
__device__ float g_ba   [(size_t)TOK * 64];
__device__ float g_conv [(size_t)TOK * CONVD];
__device__ float g_qn   [(size_t)TOK * KEYD];
__device__ float g_kn   [(size_t)TOK * KEYD];
__device__ float g_beta [(size_t)TOK * NV];
__device__ float g_gdec [(size_t)TOK * NV];
__device__ float g_core [(size_t)TOK * VALD];
// bf16 hi/lo split scratch
__device__ __nv_bfloat16 g_xhi [(size_t)TOK * HID];
__device__ __nv_bfloat16 g_xlo [(size_t)TOK * HID];
__device__ __nv_bfloat16 g_w1hi[(size_t)PQKVZ * HID];
__device__ __nv_bfloat16 g_w1lo[(size_t)PQKVZ * HID];
__device__ __nv_bfloat16 g_w2hi[(size_t)HID * VALD];
__device__ __nv_bfloat16 g_w2lo[(size_t)HID * VALD];
__device__ __nv_bfloat16 g_ghi [(size_t)TOK * VALD];
__device__ __nv_bfloat16 g_glo [(size_t)TOK * VALD];

// ---------------- helpers ----------------
__device__ __forceinline__ uint32_t smem_u32(const void* p) {
    uint32_t r;
    asm("{ .reg .u64 t; cvta.to.shared.u64 t, %1; cvt.u32.u64 %0, t; }" : "=r"(r) : "l"(p));
    return r;
}
__device__ __forceinline__ void cpasync16(uint32_t s, const void* g) {
    asm volatile("cp.async.cg.shared.global [%0], [%1], 16;" :: "r"(s), "l"(g));
}
__device__ __forceinline__ uint32_t lds32(uint32_t a) {
    uint32_t v; asm volatile("ld.shared.b32 %0, [%1];" : "=r"(v) : "r"(a)); return v;
}
__device__ __forceinline__ void mma16816(float* c, const uint32_t* a, const uint32_t* b) {
    asm volatile(
        "mma.sync.aligned.m16n8k16.row.col.f32.bf16.bf16.f32 "
        "{%0,%1,%2,%3}, {%4,%5,%6,%7}, {%8,%9}, {%0,%1,%2,%3};"
        : "+f"(c[0]), "+f"(c[1]), "+f"(c[2]), "+f"(c[3])
        : "r"(a[0]), "r"(a[1]), "r"(a[2]), "r"(a[3]), "r"(b[0]), "r"(b[1]));
}
// f32x2 packed math
__device__ __forceinline__ unsigned long long pk2(float a, float b) {
    unsigned long long r; asm("mov.b64 %0, {%1, %2};" : "=l"(r) : "f"(a), "f"(b)); return r;
}
__device__ __forceinline__ unsigned long long fma2(unsigned long long a, unsigned long long b, unsigned long long c) {
    unsigned long long d; asm("fma.rn.f32x2 %0, %1, %2, %3;" : "=l"(d) : "l"(a), "l"(b), "l"(c)); return d;
}
__device__ __forceinline__ unsigned long long mul2(unsigned long long a, unsigned long long b) {
    unsigned long long d; asm("mul.rn.f32x2 %0, %1, %2;" : "=l"(d) : "l"(a), "l"(b)); return d;
}
__device__ __forceinline__ float hadd2(unsigned long long v) {
    float a, b; asm("mov.b64 {%0, %1}, %2;" : "=f"(a), "=f"(b) : "l"(v)); return a + b;
}

// ---------------- split fp32 -> bf16 hi/lo ----------------
__global__ __launch_bounds__(256) void split_bf16(const float* __restrict__ src,
                                                  __nv_bfloat16* __restrict__ hi,
                                                  __nv_bfloat16* __restrict__ lo) {
    size_t i = ((size_t)blockIdx.x * blockDim.x + threadIdx.x) * 4;
    float4 v = *(const float4*)(src + i);
    __nv_bfloat16 h0 = __float2bfloat16(v.x), h1 = __float2bfloat16(v.y);
    __nv_bfloat16 h2 = __float2bfloat16(v.z), h3 = __float2bfloat16(v.w);
    __nv_bfloat16 l0 = __float2bfloat16(v.x - __bfloat162float(h0));
    __nv_bfloat16 l1 = __float2bfloat16(v.y - __bfloat162float(h1));
    __nv_bfloat16 l2 = __float2bfloat16(v.z - __bfloat162float(h2));
    __nv_bfloat16 l3 = __float2bfloat16(v.w - __bfloat162float(h3));
    __nv_bfloat162* hp = (__nv_bfloat162*)(hi + i);
    __nv_bfloat162* lp = (__nv_bfloat162*)(lo + i);
    hp[0] = __nv_bfloat162(h0, h1); hp[1] = __nv_bfloat162(h2, h3);
    lp[0] = __nv_bfloat162(l0, l1); lp[1] = __nv_bfloat162(l2, l3);
}

// ---------------- mma.sync bf16x3 GEMM (NT): C[m,n] = sum_k A[m,k]*B[n,k] ----------------
#define TSTRIDE 80
#define TILE_B  (128 * TSTRIDE)
#define STAGE_B (4 * TILE_B)
#define GSMEM   (2 * STAGE_B)

__global__ __launch_bounds__(256, 2)
void gemm_bf16x3(const __nv_bfloat16* __restrict__ Ah, const __nv_bfloat16* __restrict__ Al,
                 const __nv_bfloat16* __restrict__ Bh, const __nv_bfloat16* __restrict__ Bl,
                 float* __restrict__ C, int M, int N, int K) {
    extern __shared__ char sm[];
    const uint32_t sb = smem_u32(sm);
    const int tid = threadIdx.x;
    const int lane = tid & 31, wid = tid >> 5;
    const int bm = blockIdx.x * 128, bn = blockIdx.y * 128;
    const int wm = (wid & 1) * 64, wn = (wid >> 1) * 32;
    const int grp = lane >> 2, qid = lane & 3;

    float c[4][4][4];
    #pragma unroll
    for (int i = 0; i < 4; i++)
        #pragma unroll
        for (int j = 0; j < 4; j++)
            #pragma unroll
            for (int r = 0; r < 4; r++) c[i][j][r] = 0.f;

    const int niter = K >> 5;

    auto issue = [&](int kblk, int buf) {
        const int k0 = kblk * 32;
        #pragma unroll
        for (int i = 0; i < 2; i++) {
            int chunk = tid + i * 256;
            int row = chunk >> 2, c16 = chunk & 3;
            size_t ga = (size_t)(bm + row) * K + k0 + c16 * 8;
            size_t gb = (size_t)(bn + row) * K + k0 + c16 * 8;
            uint32_t so = sb + buf * STAGE_B + row * TSTRIDE + c16 * 16;
            cpasync16(so,              Ah + ga);
            cpasync16(so + TILE_B,     Al + ga);
            cpasync16(so + 2 * TILE_B, Bh + gb);
            cpasync16(so + 3 * TILE_B, Bl + gb);
        }
    };

    issue(0, 0);
    asm volatile("cp.async.commit_group;" ::: "memory");
    issue(1, 1);
    asm volatile("cp.async.commit_group;" ::: "memory");

    for (int it = 0; it < niter; it++) {
        asm volatile("cp.async.wait_group 1;" ::: "memory");
        __syncthreads();
        const int buf = it & 1;
        const uint32_t base = sb + buf * STAGE_B;

        #pragma unroll
        for (int ks = 0; ks < 2; ks++) {
            const uint32_t koff = ks * 32;
            uint32_t ah[4][4], bh[4][2];
            #pragma unroll
            for (int i = 0; i < 4; i++) {
                uint32_t r0 = base + (uint32_t)(wm + i * 16 + grp) * TSTRIDE + qid * 4 + koff;
                ah[i][0] = lds32(r0);
                ah[i][1] = lds32(r0 + 8 * TSTRIDE);
                ah[i][2] = lds32(r0 + 16);
                ah[i][3] = lds32(r0 + 8 * TSTRIDE + 16);
            }
            #pragma unroll
            for (int j = 0; j < 4; j++) {
                uint32_t rb = base + 2 * TILE_B + (uint32_t)(wn + j * 8 + grp) * TSTRIDE + qid * 4 + koff;
                bh[j][0] = lds32(rb);
                bh[j][1] = lds32(rb + 16);
            }
            // phase 1: hh
            #pragma unroll
            for (int i = 0; i < 4; i++)
                #pragma unroll
                for (int j = 0; j < 4; j++) mma16816(c[i][j], ah[i], bh[j]);
            // phase 2: lh (A-lo x B-hi); al fragments transient
            {
                uint32_t al[4][4];
                #pragma unroll
                for (int i = 0; i < 4; i++) {
                    uint32_t r0 = base + TILE_B + (uint32_t)(wm + i * 16 + grp) * TSTRIDE + qid * 4 + koff;
                    al[i][0] = lds32(r0);
                    al[i][1] = lds32(r0 + 8 * TSTRIDE);
                    al[i][2] = lds32(r0 + 16);
                    al[i][3] = lds32(r0 + 8 * TSTRIDE + 16);
                }
                #pragma unroll
                for (int i = 0; i < 4; i++)
                    #pragma unroll
                    for (int j = 0; j < 4; j++) mma16816(c[i][j], al[i], bh[j]);
            }
            // phase 3: hl (A-hi x B-lo); bl fragments transient
            {
                uint32_t bl[4][2];
                #pragma unroll
                for (int j = 0; j < 4; j++) {
                    uint32_t rb = base + 3 * TILE_B + (uint32_t)(wn + j * 8 + grp) * TSTRIDE + qid * 4 + koff;
                    bl[j][0] = lds32(rb);
                    bl[j][1] = lds32(rb + 16);
                }
                #pragma unroll
                for (int i = 0; i < 4; i++)
                    #pragma unroll
                    for (int j = 0; j < 4; j++) mma16816(c[i][j], ah[i], bl[j]);
            }
        }
        __syncthreads();
        if (it + 2 < niter) issue(it + 2, buf);
        asm volatile("cp.async.commit_group;" ::: "memory");
    }

    #pragma unroll
    for (int i = 0; i < 4; i++) {
        const int row0 = bm + wm + i * 16 + grp;
        #pragma unroll
        for (int j = 0; j < 4; j++) {
            const int col = bn + wn + j * 8 + qid * 2;
            float2 v01 = make_float2(c[i][j][0], c[i][j][1]);
            float2 v23 = make_float2(c[i][j][2], c[i][j][3]);
            *(float2*)(C + (size_t)row0 * N + col)       = v01;
            *(float2*)(C + (size_t)(row0 + 8) * N + col) = v23;
        }
    }
}

// ---------------- SIMT SGEMM (NT) for tiny ba GEMM ----------------
#define BM 128
#define BN 128
#define BKK 16
__global__ __launch_bounds__(256) void sgemm_nt(const float* __restrict__ A,
                                                const float* __restrict__ B,
                                                float* __restrict__ C,
                                                int M, int N, int K) {
    __shared__ float As[BKK][BM];
    __shared__ float Bs[BKK][BN];
    const int tid = threadIdx.x;
    const int bm = blockIdx.y * BM;
    const int bn = blockIdx.x * BN;
    const int tx = tid & 15;
    const int ty = tid >> 4;
    const int lrow = tid >> 2;
    const int lk4 = (tid & 3) * 4;

    float acc[8][8];
    #pragma unroll
    for (int i = 0; i < 8; i++)
        #pragma unroll
        for (int j = 0; j < 8; j++) acc[i][j] = 0.f;

    for (int k0 = 0; k0 < K; k0 += BKK) {
        #pragma unroll
        for (int it = 0; it < 2; it++) {
            int row = lrow + it * 64;
            float4 v = *(const float4*)(A + (size_t)(bm + row) * K + k0 + lk4);
            As[lk4 + 0][row] = v.x; As[lk4 + 1][row] = v.y;
            As[lk4 + 2][row] = v.z; As[lk4 + 3][row] = v.w;
        }
        #pragma unroll
        for (int it = 0; it < 2; it++) {
            int row = lrow + it * 64;
            int gn = bn + row;
            float4 v = make_float4(0.f, 0.f, 0.f, 0.f);
            if (gn < N) v = *(const float4*)(B + (size_t)gn * K + k0 + lk4);
            Bs[lk4 + 0][row] = v.x; Bs[lk4 + 1][row] = v.y;
            Bs[lk4 + 2][row] = v.z; Bs[lk4 + 3][row] = v.w;
        }
        __syncthreads();
        #pragma unroll
        for (int kk = 0; kk < BKK; kk++) {
            float ar[8], br[8];
            #pragma unroll
            for (int i = 0; i < 8; i++) ar[i] = As[kk][ty * 8 + i];
            #pragma unroll
            for (int j = 0; j < 8; j++) br[j] = Bs[kk][tx * 8 + j];
            #pragma unroll
            for (int i = 0; i < 8; i++)
                #pragma unroll
                for (int j = 0; j < 8; j++)
                    acc[i][j] = fmaf(ar[i], br[j], acc[i][j]);
        }
        __syncthreads();
    }
    #pragma unroll
    for (int i = 0; i < 8; i++) {
        int gm = bm + ty * 8 + i;
        #pragma unroll
        for (int j = 0; j < 8; j++) {
            int gn = bn + tx * 8 + j;
            if (gn < N) C[(size_t)gm * N + gn] = acc[i][j];
        }
    }
}

// ---------------- depthwise causal conv1d (K=4) + SiLU ----------------
__global__ void conv_silu_kernel(const float* __restrict__ qkvz,
                                 const float* __restrict__ cw,
                                 float* __restrict__ out) {
    size_t idx = (size_t)blockIdx.x * blockDim.x + threadIdx.x;
    int c = (int)(idx & (CONVD - 1));
    size_t t = idx >> 13;
    int s = (int)(t & (SEQ - 1));
    size_t b = t >> 11;
    const float* base = qkvz + (b * SEQ) * (size_t)PQKVZ + c;
    float w0 = cw[c * 4 + 0], w1 = cw[c * 4 + 1], w2 = cw[c * 4 + 2], w3 = cw[c * 4 + 3];
    float acc = w3 * base[(size_t)s * PQKVZ];
    if (s >= 1) acc = fmaf(w2, base[(size_t)(s - 1) * PQKVZ], acc);
    if (s >= 2) acc = fmaf(w1, base[(size_t)(s - 2) * PQKVZ], acc);
    if (s >= 3) acc = fmaf(w0, base[(size_t)(s - 3) * PQKVZ], acc);
    out[idx] = acc / (1.f + expf(-acc));
}

// ---------------- l2norm(q,k) + gates ----------------
__global__ __launch_bounds__(512) void prep_kernel(const float* __restrict__ conv,
                                                   const float* __restrict__ ba,
                                                   const float* __restrict__ dt_bias,
                                                   const float* __restrict__ A_log,
                                                   float* __restrict__ qn,
                                                   float* __restrict__ kn,
                                                   float* __restrict__ beta,
                                                   float* __restrict__ gdec) {
    size_t t = blockIdx.x;
    int w = threadIdx.x >> 5;
    int l = threadIdx.x & 31;
    const float* cq = conv + t * CONVD + w * DK;
    const float* ck = conv + t * CONVD + KEYD + w * DK;
    float qv[4], kv[4];
    float sq = 0.f, sk = 0.f;
    #pragma unroll
    for (int i = 0; i < 4; i++) {
        qv[i] = cq[l + 32 * i]; sq = fmaf(qv[i], qv[i], sq);
        kv[i] = ck[l + 32 * i]; sk = fmaf(kv[i], kv[i], sk);
    }
    #pragma unroll
    for (int o = 16; o; o >>= 1) {
        sq += __shfl_xor_sync(0xffffffffu, sq, o);
        sk += __shfl_xor_sync(0xffffffffu, sk, o);
    }
    float rq = rsqrtf(sq + EPSF), rk = rsqrtf(sk + EPSF);
    #pragma unroll
    for (int i = 0; i < 4; i++) {
        qn[(t * NK + w) * DK + l + 32 * i] = qv[i] * rq;
        kn[(t * NK + w) * DK + l + 32 * i] = kv[i] * rk;
    }
    if (threadIdx.x < NV) {
        int h = threadIdx.x;
        float bv = ba[t * 64 + h];
        float av = ba[t * 64 + NV + h];
        beta[t * NV + h] = 1.f / (1.f + expf(-bv));
        float xx = av + dt_bias[h];
        float sp = (xx > 20.f) ? xx : log1pf(expf(xx));
        gdec[t * NV + h] = expf(-expf(A_log[h]) * sp);
    }
}

// ---------------- gated delta-rule scan (f32x2 packed) ----------------
__global__ __launch_bounds__(128) void scan_kernel(const float* __restrict__ qn,
                                                   const float* __restrict__ kn,
                                                   const float* __restrict__ conv,
                                                   const float* __restrict__ beta,
                                                   const float* __restrict__ gdec,
                                                   float* __restrict__ core) {
    const int h = blockIdx.x;
    const int b = blockIdx.y;
    const int nk = h >> 1;
    const int tid = threadIdx.x;
    __shared__ ulonglong2 ks[32], qs[32];
    unsigned long long st[64];
    #pragma unroll
    for (int j = 0; j < 64; j++) st[j] = 0ull;

    for (int s = 0; s < SEQ; s++) {
        size_t t = (size_t)b * SEQ + s;
        __syncthreads();
        if (tid < 32)
            ks[tid] = ((const ulonglong2*)(kn + (t * NK + nk) * DK))[tid];
        else if (tid < 64)
            qs[tid - 32] = ((const ulonglong2*)(qn + (t * NK + nk) * DK))[tid - 32];
        float vt = conv[t * CONVD + KEYD * 2 + h * DV + tid];
        float ge = gdec[t * NV + h];
        float bt = beta[t * NV + h];
        __syncthreads();

        // kvd = k . state   (4 independent accumulator chains)
        unsigned long long a0 = 0ull, a1 = 0ull, a2 = 0ull, a3 = 0ull;
        #pragma unroll
        for (int j = 0; j < 32; j += 2) {
            ulonglong2 k0 = ks[j], k1 = ks[j + 1];
            a0 = fma2(k0.x, st[2 * j + 0], a0);
            a1 = fma2(k0.y, st[2 * j + 1], a1);
            a2 = fma2(k1.x, st[2 * j + 2], a2);
            a3 = fma2(k1.y, st[2 * j + 3], a3);
        }
        float kvd = (hadd2(a0) + hadd2(a1)) + (hadd2(a2) + hadd2(a3));
        float delta = bt * (vt - ge * kvd);
        unsigned long long ge2 = pk2(ge, ge);
        unsigned long long d2 = pk2(delta, delta);

        unsigned long long o0 = 0ull, o1 = 0ull, o2 = 0ull, o3 = 0ull;
        #pragma unroll
        for (int j = 0; j < 32; j += 2) {
            ulonglong2 k0 = ks[j], k1 = ks[j + 1];
            ulonglong2 q0 = qs[j], q1 = qs[j + 1];
            st[2 * j + 0] = fma2(ge2, st[2 * j + 0], mul2(k0.x, d2));
            o0 = fma2(q0.x, st[2 * j + 0], o0);
            st[2 * j + 1] = fma2(ge2, st[2 * j + 1], mul2(k0.y, d2));
            o1 = fma2(q0.y, st[2 * j + 1], o1);
            st[2 * j + 2] = fma2(ge2, st[2 * j + 2], mul2(k1.x, d2));
            o2 = fma2(q1.x, st[2 * j + 2], o2);
            st[2 * j + 3] = fma2(ge2, st[2 * j + 3], mul2(k1.y, d2));
            o3 = fma2(q1.y, st[2 * j + 3], o3);
        }
        core[t * VALD + h * DV + tid] = (hadd2(o0) + hadd2(o1)) + (hadd2(o2) + hadd2(o3));
    }
}

// ---------------- RMSNorm(1+w) + silu(z) gate -> bf16 hi/lo ----------------
__global__ __launch_bounds__(256) void rmsnorm_gate_kernel(const float* __restrict__ core,
                                                           const float* __restrict__ qkvz,
                                                           const float* __restrict__ norm_w,
                                                           __nv_bfloat16* __restrict__ ghi,
                                                           __nv_bfloat16* __restrict__ glo) {
    size_t t = blockIdx.x;
    __shared__ float red[8];
    __shared__ float s_scale;
    const float* row = core + t * VALD;
    const float* zrow = qkvz + t * PQKVZ + 2 * KEYD + VALD;
    float ss = 0.f;
    for (int c = threadIdx.x; c < VALD; c += 256) { float v = row[c]; ss = fmaf(v, v, ss); }
    #pragma unroll
    for (int o = 16; o; o >>= 1) ss += __shfl_xor_sync(0xffffffffu, ss, o);
    if ((threadIdx.x & 31) == 0) red[threadIdx.x >> 5] = ss;
    __syncthreads();
    if (threadIdx.x == 0) {
        float tot = 0.f;
        #pragma unroll
        for (int i = 0; i < 8; i++) tot += red[i];
        s_scale = rsqrtf(tot * (1.f / VALD) + EPSF);
    }
    __syncthreads();
    float sc = s_scale;
    for (int c = threadIdx.x; c < VALD; c += 256) {
        float z = zrow[c];
        float sz = z / (1.f + expf(-z));
        float val = row[c] * sc * (1.f + norm_w[c]) * sz;
        __nv_bfloat16 hv = __float2bfloat16(val);
        ghi[t * VALD + c] = hv;
        glo[t * VALD + c] = __float2bfloat16(val - __bfloat162float(hv));
    }
}

// ---------------- launch ----------------
extern "C" void kernel_launch(void* const* d_in, const int* in_sizes, int n_in,
                              void* d_out, int out_size) {
    const float* x       = (const float*)d_in[0];
    const float* W_qkvz  = (const float*)d_in[1];
    const float* W_ba    = (const float*)d_in[2];
    const float* conv_w  = (const float*)d_in[3];
    const float* dt_bias = (const float*)d_in[4];
    const float* A_log   = (const float*)d_in[5];
    const float* norm_w  = (const float*)d_in[6];
    const float* W_out   = (const float*)d_in[7];
    float* out = (float*)d_out;

    float *p_qkvz, *p_ba, *p_conv, *p_qn, *p_kn, *p_beta, *p_g, *p_core;
    __nv_bfloat16 *p_xhi, *p_xlo, *p_w1hi, *p_w1lo, *p_w2hi, *p_w2lo, *p_ghi, *p_glo;
    cudaGetSymbolAddress((void**)&p_qkvz,  g_qkvz);
    cudaGetSymbolAddress((void**)&p_ba,    g_ba);
    cudaGetSymbolAddress((void**)&p_conv,  g_conv);
    cudaGetSymbolAddress((void**)&p_qn,    g_qn);
    cudaGetSymbolAddress((void**)&p_kn,    g_kn);
    cudaGetSymbolAddress((void**)&p_beta,  g_beta);
    cudaGetSymbolAddress((void**)&p_g,     g_gdec);
    cudaGetSymbolAddress((void**)&p_core,  g_core);
    cudaGetSymbolAddress((void**)&p_xhi,  g_xhi);
    cudaGetSymbolAddress((void**)&p_xlo,  g_xlo);
    cudaGetSymbolAddress((void**)&p_w1hi, g_w1hi);
    cudaGetSymbolAddress((void**)&p_w1lo, g_w1lo);
    cudaGetSymbolAddress((void**)&p_w2hi, g_w2hi);
    cudaGetSymbolAddress((void**)&p_w2lo, g_w2lo);
    cudaGetSymbolAddress((void**)&p_ghi,  g_ghi);
    cudaGetSymbolAddress((void**)&p_glo,  g_glo);

    cudaFuncSetAttribute(gemm_bf16x3, cudaFuncAttributeMaxDynamicSharedMemorySize, GSMEM);

    // splits for GEMM operands
    split_bf16<<<(TOK * (size_t)HID) / 1024, 256>>>(x, p_xhi, p_xlo);
    split_bf16<<<((size_t)PQKVZ * HID) / 1024, 256>>>(W_qkvz, p_w1hi, p_w1lo);
    split_bf16<<<((size_t)HID * VALD) / 1024, 256>>>(W_out, p_w2hi, p_w2lo);

    // 1) qkvz = x @ W_qkvz^T  (mma.sync bf16x3)
    gemm_bf16x3<<<dim3(TOK / 128, PQKVZ / 128), 256, GSMEM>>>(
        p_xhi, p_xlo, p_w1hi, p_w1lo, p_qkvz, TOK, PQKVZ, HID);
    // 2) ba = x @ W_ba^T (SIMT, tiny)
    sgemm_nt<<<dim3(1, TOK / BM), 256>>>(x, W_ba, p_ba, TOK, 64, HID);
    // 3) conv + silu
    conv_silu_kernel<<<(TOK * (size_t)CONVD) / 256, 256>>>(p_qkvz, conv_w, p_conv);
    // 4) l2norm + gates
    prep_kernel<<<TOK, 512>>>(p_conv, p_ba, dt_bias, A_log, p_qn, p_kn, p_beta, p_g);
    // 5) delta-rule scan (f32x2 packed)
    scan_kernel<<<dim3(NV, BATCH), 128>>>(p_qn, p_kn, p_conv, p_beta, p_g, p_core);
    // 6) rmsnorm + gate -> bf16 hi/lo directly
    rmsnorm_gate_kernel<<<TOK, 256>>>(p_core, p_qkvz, norm_w, p_ghi, p_glo);
    // 7) out = gated @ W_out^T (mma.sync bf16x3)
    gemm_bf16x3<<<dim3(TOK / 128, HID / 128), 256, GSMEM>>>(
        p_ghi, p_glo, p_w2hi, p_w2lo, out, TOK, HID, VALD);
}

// round 6
// speedup vs baseline: 3.2532x; 1.2610x over previous
#include <cuda_runtime.h>
#include <cuda_bf16.h>
#include <cstdint>

// ---------------- model dims ----------------
#define BATCH 2
#define SEQ   2048
#define TOK   (BATCH*SEQ)        // 4096
#define HID   2048
#define NK    16
#define NV    32
#define DK    128
#define DV    128
#define KEYD  2048               // NK*DK
#define VALD  4096               // NV*DV
#define CONVD 8192               // 2*KEYD + VALD
#define PQKVZ 12288              // 2*KEYD + 2*VALD
#define EPSF  1e-6f

// ---------------- scratch (device globals; no allocation) ----------------
__device__ float g_qkvz [(size_t)TOK * PQKVZ];
__device__ float g_ba   [(size_t)TOK * 64];
__device__ float g_conv [(size_t)TOK * CONVD];
__device__ float g_qn   [(size_t)TOK * KEYD];
__device__ float g_kn   [(size_t)TOK * KEYD];
__device__ float g_beta [(size_t)TOK * NV];
__device__ float g_gdec [(size_t)TOK * NV];
__device__ float g_core [(size_t)TOK * VALD];
// bf16 hi/lo split scratch
__device__ __nv_bfloat16 g_xhi [(size_t)TOK * HID];
__device__ __nv_bfloat16 g_xlo [(size_t)TOK * HID];
__device__ __nv_bfloat16 g_w1hi[(size_t)PQKVZ * HID];
__device__ __nv_bfloat16 g_w1lo[(size_t)PQKVZ * HID];
__device__ __nv_bfloat16 g_w2hi[(size_t)HID * VALD];
__device__ __nv_bfloat16 g_w2lo[(size_t)HID * VALD];
__device__ __nv_bfloat16 g_ghi [(size_t)TOK * VALD];
__device__ __nv_bfloat16 g_glo [(size_t)TOK * VALD];

// ---------------- helpers ----------------
__device__ __forceinline__ uint32_t smem_u32(const void* p) {
    uint32_t r;
    asm("{ .reg .u64 t; cvta.to.shared.u64 t, %1; cvt.u32.u64 %0, t; }" : "=r"(r) : "l"(p));
    return r;
}
__device__ __forceinline__ void cpasync16(uint32_t s, const void* g) {
    asm volatile("cp.async.cg.shared.global [%0], [%1], 16;" :: "r"(s), "l"(g));
}
__device__ __forceinline__ void ldmx4(uint32_t* r, uint32_t addr) {
    asm volatile("ldmatrix.sync.aligned.m8n8.x4.shared.b16 {%0,%1,%2,%3}, [%4];"
                 : "=r"(r[0]), "=r"(r[1]), "=r"(r[2]), "=r"(r[3]) : "r"(addr));
}
__device__ __forceinline__ void mma16816(float* c, const uint32_t* a, const uint32_t* b) {
    asm volatile(
        "mma.sync.aligned.m16n8k16.row.col.f32.bf16.bf16.f32 "
        "{%0,%1,%2,%3}, {%4,%5,%6,%7}, {%8,%9}, {%0,%1,%2,%3};"
        : "+f"(c[0]), "+f"(c[1]), "+f"(c[2]), "+f"(c[3])
        : "r"(a[0]), "r"(a[1]), "r"(a[2]), "r"(a[3]), "r"(b[0]), "r"(b[1]));
}
// f32x2 packed math
__device__ __forceinline__ unsigned long long pk2(float a, float b) {
    unsigned long long r; asm("mov.b64 %0, {%1, %2};" : "=l"(r) : "f"(a), "f"(b)); return r;
}
__device__ __forceinline__ unsigned long long fma2(unsigned long long a, unsigned long long b, unsigned long long c) {
    unsigned long long d; asm("fma.rn.f32x2 %0, %1, %2, %3;" : "=l"(d) : "l"(a), "l"(b), "l"(c)); return d;
}
__device__ __forceinline__ unsigned long long mul2(unsigned long long a, unsigned long long b) {
    unsigned long long d; asm("mul.rn.f32x2 %0, %1, %2;" : "=l"(d) : "l"(a), "l"(b)); return d;
}
__device__ __forceinline__ float hadd2(unsigned long long v) {
    float a, b; asm("mov.b64 {%0, %1}, %2;" : "=f"(a), "=f"(b) : "l"(v)); return a + b;
}

// ---------------- split fp32 -> bf16 hi/lo ----------------
__global__ __launch_bounds__(256) void split_bf16(const float* __restrict__ src,
                                                  __nv_bfloat16* __restrict__ hi,
                                                  __nv_bfloat16* __restrict__ lo) {
    size_t i = ((size_t)blockIdx.x * blockDim.x + threadIdx.x) * 4;
    float4 v = *(const float4*)(src + i);
    __nv_bfloat16 h0 = __float2bfloat16(v.x), h1 = __float2bfloat16(v.y);
    __nv_bfloat16 h2 = __float2bfloat16(v.z), h3 = __float2bfloat16(v.w);
    __nv_bfloat16 l0 = __float2bfloat16(v.x - __bfloat162float(h0));
    __nv_bfloat16 l1 = __float2bfloat16(v.y - __bfloat162float(h1));
    __nv_bfloat16 l2 = __float2bfloat16(v.z - __bfloat162float(h2));
    __nv_bfloat16 l3 = __float2bfloat16(v.w - __bfloat162float(h3));
    __nv_bfloat162* hp = (__nv_bfloat162*)(hi + i);
    __nv_bfloat162* lp = (__nv_bfloat162*)(lo + i);
    hp[0] = __nv_bfloat162(h0, h1); hp[1] = __nv_bfloat162(h2, h3);
    lp[0] = __nv_bfloat162(l0, l1); lp[1] = __nv_bfloat162(l2, l3);
}

// ---------------- mma.sync bf16x3 GEMM (NT): C[m,n] = sum_k A[m,k]*B[n,k] ----------------
#define TSTRIDE 80
#define TILE_B  (128 * TSTRIDE)
#define STAGE_B (4 * TILE_B)
#define GSMEM   (2 * STAGE_B)

__global__ __launch_bounds__(256, 2)
void gemm_bf16x3(const __nv_bfloat16* __restrict__ Ah, const __nv_bfloat16* __restrict__ Al,
                 const __nv_bfloat16* __restrict__ Bh, const __nv_bfloat16* __restrict__ Bl,
                 float* __restrict__ C, int M, int N, int K) {
    extern __shared__ char sm[];
    const uint32_t sb = smem_u32(sm);
    const int tid = threadIdx.x;
    const int lane = tid & 31, wid = tid >> 5;
    const int bm = blockIdx.x * 128, bn = blockIdx.y * 128;
    const int wm = (wid & 1) * 64, wn = (wid >> 1) * 32;
    const int grp = lane >> 2, qid = lane & 3;

    // ldmatrix lane address components
    const uint32_t a_row = (uint32_t)(lane & 15);
    const uint32_t a_c16 = (uint32_t)((lane >> 4) * 16);
    const uint32_t b_row = (uint32_t)((lane & 7) + ((lane >> 4) & 1) * 8);
    const uint32_t b_c16 = (uint32_t)(((lane >> 3) & 1) * 16);

    float c[4][4][4];
    #pragma unroll
    for (int i = 0; i < 4; i++)
        #pragma unroll
        for (int j = 0; j < 4; j++)
            #pragma unroll
            for (int r = 0; r < 4; r++) c[i][j][r] = 0.f;

    const int niter = K >> 5;

    auto issue = [&](int kblk, int buf) {
        const int k0 = kblk * 32;
        #pragma unroll
        for (int i = 0; i < 2; i++) {
            int chunk = tid + i * 256;
            int row = chunk >> 2, c16 = chunk & 3;
            size_t ga = (size_t)(bm + row) * K + k0 + c16 * 8;
            size_t gb = (size_t)(bn + row) * K + k0 + c16 * 8;
            uint32_t so = sb + buf * STAGE_B + row * TSTRIDE + c16 * 16;
            cpasync16(so,              Ah + ga);
            cpasync16(so + TILE_B,     Al + ga);
            cpasync16(so + 2 * TILE_B, Bh + gb);
            cpasync16(so + 3 * TILE_B, Bl + gb);
        }
    };

    issue(0, 0);
    asm volatile("cp.async.commit_group;" ::: "memory");
    issue(1, 1);
    asm volatile("cp.async.commit_group;" ::: "memory");

    for (int it = 0; it < niter; it++) {
        asm volatile("cp.async.wait_group 1;" ::: "memory");
        __syncthreads();
        const int buf = it & 1;
        const uint32_t base = sb + buf * STAGE_B;

        #pragma unroll
        for (int ks = 0; ks < 2; ks++) {
            const uint32_t koff = ks * 32;
            const uint32_t abase = base + (uint32_t)(wm + a_row) * TSTRIDE + koff + a_c16;
            const uint32_t bbase = base + 2 * TILE_B + (uint32_t)(wn + b_row) * TSTRIDE + koff + b_c16;
            uint32_t ah[4][4], bh[2][4];
            #pragma unroll
            for (int i = 0; i < 4; i++) ldmx4(ah[i], abase + (uint32_t)(i * 16) * TSTRIDE);
            #pragma unroll
            for (int J = 0; J < 2; J++) ldmx4(bh[J], bbase + (uint32_t)(J * 16) * TSTRIDE);
            // phase 1: hh
            #pragma unroll
            for (int i = 0; i < 4; i++)
                #pragma unroll
                for (int j = 0; j < 4; j++) mma16816(c[i][j], ah[i], &bh[j >> 1][(j & 1) * 2]);
            // phase 2: lh (A-lo x B-hi)
            {
                uint32_t al[4][4];
                #pragma unroll
                for (int i = 0; i < 4; i++) ldmx4(al[i], abase + TILE_B + (uint32_t)(i * 16) * TSTRIDE);
                #pragma unroll
                for (int i = 0; i < 4; i++)
                    #pragma unroll
                    for (int j = 0; j < 4; j++) mma16816(c[i][j], al[i], &bh[j >> 1][(j & 1) * 2]);
            }
            // phase 3: hl (A-hi x B-lo)
            {
                uint32_t bl[2][4];
                #pragma unroll
                for (int J = 0; J < 2; J++) ldmx4(bl[J], bbase + TILE_B + (uint32_t)(J * 16) * TSTRIDE);
                #pragma unroll
                for (int i = 0; i < 4; i++)
                    #pragma unroll
                    for (int j = 0; j < 4; j++) mma16816(c[i][j], ah[i], &bl[j >> 1][(j & 1) * 2]);
            }
        }
        __syncthreads();
        if (it + 2 < niter) issue(it + 2, buf);
        asm volatile("cp.async.commit_group;" ::: "memory");
    }

    #pragma unroll
    for (int i = 0; i < 4; i++) {
        const int row0 = bm + wm + i * 16 + grp;
        #pragma unroll
        for (int j = 0; j < 4; j++) {
            const int col = bn + wn + j * 8 + qid * 2;
            float2 v01 = make_float2(c[i][j][0], c[i][j][1]);
            float2 v23 = make_float2(c[i][j][2], c[i][j][3]);
            *(float2*)(C + (size_t)row0 * N + col)       = v01;
            *(float2*)(C + (size_t)(row0 + 8) * N + col) = v23;
        }
    }
}

// ---------------- SIMT SGEMM (NT) for tiny ba GEMM ----------------
#define BM 128
#define BN 128
#define BKK 16
__global__ __launch_bounds__(256) void sgemm_nt(const float* __restrict__ A,
                                                const float* __restrict__ B,
                                                float* __restrict__ C,
                                                int M, int N, int K) {
    __shared__ float As[BKK][BM];
    __shared__ float Bs[BKK][BN];
    const int tid = threadIdx.x;
    const int bm = blockIdx.y * BM;
    const int bn = blockIdx.x * BN;
    const int tx = tid & 15;
    const int ty = tid >> 4;
    const int lrow = tid >> 2;
    const int lk4 = (tid & 3) * 4;

    float acc[8][8];
    #pragma unroll
    for (int i = 0; i < 8; i++)
        #pragma unroll
        for (int j = 0; j < 8; j++) acc[i][j] = 0.f;

    for (int k0 = 0; k0 < K; k0 += BKK) {
        #pragma unroll
        for (int it = 0; it < 2; it++) {
            int row = lrow + it * 64;
            float4 v = *(const float4*)(A + (size_t)(bm + row) * K + k0 + lk4);
            As[lk4 + 0][row] = v.x; As[lk4 + 1][row] = v.y;
            As[lk4 + 2][row] = v.z; As[lk4 + 3][row] = v.w;
        }
        #pragma unroll
        for (int it = 0; it < 2; it++) {
            int row = lrow + it * 64;
            int gn = bn + row;
            float4 v = make_float4(0.f, 0.f, 0.f, 0.f);
            if (gn < N) v = *(const float4*)(B + (size_t)gn * K + k0 + lk4);
            Bs[lk4 + 0][row] = v.x; Bs[lk4 + 1][row] = v.y;
            Bs[lk4 + 2][row] = v.z; Bs[lk4 + 3][row] = v.w;
        }
        __syncthreads();
        #pragma unroll
        for (int kk = 0; kk < BKK; kk++) {
            float ar[8], br[8];
            #pragma unroll
            for (int i = 0; i < 8; i++) ar[i] = As[kk][ty * 8 + i];
            #pragma unroll
            for (int j = 0; j < 8; j++) br[j] = Bs[kk][tx * 8 + j];
            #pragma unroll
            for (int i = 0; i < 8; i++)
                #pragma unroll
                for (int j = 0; j < 8; j++)
                    acc[i][j] = fmaf(ar[i], br[j], acc[i][j]);
        }
        __syncthreads();
    }
    #pragma unroll
    for (int i = 0; i < 8; i++) {
        int gm = bm + ty * 8 + i;
        #pragma unroll
        for (int j = 0; j < 8; j++) {
            int gn = bn + tx * 8 + j;
            if (gn < N) C[(size_t)gm * N + gn] = acc[i][j];
        }
    }
}

// ---------------- depthwise causal conv1d (K=4) + SiLU ----------------
__global__ void conv_silu_kernel(const float* __restrict__ qkvz,
                                 const float* __restrict__ cw,
                                 float* __restrict__ out) {
    size_t idx = (size_t)blockIdx.x * blockDim.x + threadIdx.x;
    int c = (int)(idx & (CONVD - 1));
    size_t t = idx >> 13;
    int s = (int)(t & (SEQ - 1));
    size_t b = t >> 11;
    const float* base = qkvz + (b * SEQ) * (size_t)PQKVZ + c;
    float w0 = cw[c * 4 + 0], w1 = cw[c * 4 + 1], w2 = cw[c * 4 + 2], w3 = cw[c * 4 + 3];
    float acc = w3 * base[(size_t)s * PQKVZ];
    if (s >= 1) acc = fmaf(w2, base[(size_t)(s - 1) * PQKVZ], acc);
    if (s >= 2) acc = fmaf(w1, base[(size_t)(s - 2) * PQKVZ], acc);
    if (s >= 3) acc = fmaf(w0, base[(size_t)(s - 3) * PQKVZ], acc);
    out[idx] = acc / (1.f + expf(-acc));
}

// ---------------- l2norm(q,k) + gates ----------------
__global__ __launch_bounds__(512) void prep_kernel(const float* __restrict__ conv,
                                                   const float* __restrict__ ba,
                                                   const float* __restrict__ dt_bias,
                                                   const float* __restrict__ A_log,
                                                   float* __restrict__ qn,
                                                   float* __restrict__ kn,
                                                   float* __restrict__ beta,
                                                   float* __restrict__ gdec) {
    size_t t = blockIdx.x;
    int w = threadIdx.x >> 5;
    int l = threadIdx.x & 31;
    const float* cq = conv + t * CONVD + w * DK;
    const float* ck = conv + t * CONVD + KEYD + w * DK;
    float qv[4], kv[4];
    float sq = 0.f, sk = 0.f;
    #pragma unroll
    for (int i = 0; i < 4; i++) {
        qv[i] = cq[l + 32 * i]; sq = fmaf(qv[i], qv[i], sq);
        kv[i] = ck[l + 32 * i]; sk = fmaf(kv[i], kv[i], sk);
    }
    #pragma unroll
    for (int o = 16; o; o >>= 1) {
        sq += __shfl_xor_sync(0xffffffffu, sq, o);
        sk += __shfl_xor_sync(0xffffffffu, sk, o);
    }
    float rq = rsqrtf(sq + EPSF), rk = rsqrtf(sk + EPSF);
    #pragma unroll
    for (int i = 0; i < 4; i++) {
        qn[(t * NK + w) * DK + l + 32 * i] = qv[i] * rq;
        kn[(t * NK + w) * DK + l + 32 * i] = kv[i] * rk;
    }
    if (threadIdx.x < NV) {
        int h = threadIdx.x;
        float bv = ba[t * 64 + h];
        float av = ba[t * 64 + NV + h];
        beta[t * NV + h] = 1.f / (1.f + expf(-bv));
        float xx = av + dt_bias[h];
        float sp = (xx > 20.f) ? xx : log1pf(expf(xx));
        gdec[t * NV + h] = expf(-expf(A_log[h]) * sp);
    }
}

// ---------------- gated delta-rule scan v3 ----------------
// 256 threads: 2 threads per DV column (DK split 64/64), double-buffered smem k/q,
// register prefetch of next step's v/g/beta, one __syncthreads per step.
__global__ __launch_bounds__(256) void scan_kernel(const float* __restrict__ qn,
                                                   const float* __restrict__ kn,
                                                   const float* __restrict__ conv,
                                                   const float* __restrict__ beta,
                                                   const float* __restrict__ gdec,
                                                   float* __restrict__ core) {
    const int h = blockIdx.x;       // value head
    const int b = blockIdx.y;
    const int nk = h >> 1;
    const int tid = threadIdx.x;
    const int col = tid >> 1;       // DV column 0..127
    const int half = tid & 1;       // DK half 0/1
    __shared__ ulonglong2 ks[2][32], qs[2][32];
    unsigned long long st[32];      // 64 floats: DK rows half*64 .. half*64+63
    #pragma unroll
    for (int j = 0; j < 32; j++) st[j] = 0ull;

    const size_t tbase = (size_t)b * SEQ;
    // preload step 0
    if (tid < 32)
        ks[0][tid] = ((const ulonglong2*)(kn + (tbase * NK + nk) * DK))[tid];
    else if (tid < 64)
        qs[0][tid - 32] = ((const ulonglong2*)(qn + (tbase * NK + nk) * DK))[tid - 32];
    float vt = conv[tbase * CONVD + 2 * KEYD + h * DV + col];
    float ge = gdec[tbase * NV + h];
    float bt = beta[tbase * NV + h];
    __syncthreads();

    for (int s = 0; s < SEQ; s++) {
        const int buf = s & 1;
        const size_t t = tbase + s;
        // prefetch step s+1 into other buffer / registers
        float nvt = 0.f, nge = 0.f, nbt = 0.f;
        if (s + 1 < SEQ) {
            const size_t tn = t + 1;
            if (tid < 32)
                ks[buf ^ 1][tid] = ((const ulonglong2*)(kn + (tn * NK + nk) * DK))[tid];
            else if (tid < 64)
                qs[buf ^ 1][tid - 32] = ((const ulonglong2*)(qn + (tn * NK + nk) * DK))[tid - 32];
            nvt = conv[tn * CONVD + 2 * KEYD + h * DV + col];
            nge = gdec[tn * NV + h];
            nbt = beta[tn * NV + h];
        }

        const ulonglong2* kk = &ks[buf][half * 16];
        const ulonglong2* qq = &qs[buf][half * 16];

        unsigned long long a0 = 0ull, a1 = 0ull;
        #pragma unroll
        for (int j = 0; j < 16; j++) {
            ulonglong2 kj = kk[j];
            a0 = fma2(kj.x, st[2 * j + 0], a0);
            a1 = fma2(kj.y, st[2 * j + 1], a1);
        }
        float kvd = hadd2(a0) + hadd2(a1);
        kvd += __shfl_xor_sync(0xffffffffu, kvd, 1);
        float delta = bt * (vt - ge * kvd);
        unsigned long long ge2 = pk2(ge, ge);
        unsigned long long d2 = pk2(delta, delta);

        unsigned long long o0 = 0ull, o1 = 0ull;
        #pragma unroll
        for (int j = 0; j < 16; j++) {
            ulonglong2 kj = kk[j], qj = qq[j];
            st[2 * j + 0] = fma2(ge2, st[2 * j + 0], mul2(kj.x, d2));
            o0 = fma2(qj.x, st[2 * j + 0], o0);
            st[2 * j + 1] = fma2(ge2, st[2 * j + 1], mul2(kj.y, d2));
            o1 = fma2(qj.y, st[2 * j + 1], o1);
        }
        float o = hadd2(o0) + hadd2(o1);
        o += __shfl_xor_sync(0xffffffffu, o, 1);
        if (half == 0) core[t * VALD + h * DV + col] = o;

        vt = nvt; ge = nge; bt = nbt;
        __syncthreads();
    }
}

// ---------------- RMSNorm(1+w) + silu(z) gate -> bf16 hi/lo ----------------
__global__ __launch_bounds__(256) void rmsnorm_gate_kernel(const float* __restrict__ core,
                                                           const float* __restrict__ qkvz,
                                                           const float* __restrict__ norm_w,
                                                           __nv_bfloat16* __restrict__ ghi,
                                                           __nv_bfloat16* __restrict__ glo) {
    size_t t = blockIdx.x;
    __shared__ float red[8];
    __shared__ float s_scale;
    const float* row = core + t * VALD;
    const float* zrow = qkvz + t * PQKVZ + 2 * KEYD + VALD;
    float ss = 0.f;
    for (int c = threadIdx.x; c < VALD; c += 256) { float v = row[c]; ss = fmaf(v, v, ss); }
    #pragma unroll
    for (int o = 16; o; o >>= 1) ss += __shfl_xor_sync(0xffffffffu, ss, o);
    if ((threadIdx.x & 31) == 0) red[threadIdx.x >> 5] = ss;
    __syncthreads();
    if (threadIdx.x == 0) {
        float tot = 0.f;
        #pragma unroll
        for (int i = 0; i < 8; i++) tot += red[i];
        s_scale = rsqrtf(tot * (1.f / VALD) + EPSF);
    }
    __syncthreads();
    float sc = s_scale;
    for (int c = threadIdx.x; c < VALD; c += 256) {
        float z = zrow[c];
        float sz = z / (1.f + expf(-z));
        float val = row[c] * sc * (1.f + norm_w[c]) * sz;
        __nv_bfloat16 hv = __float2bfloat16(val);
        ghi[t * VALD + c] = hv;
        glo[t * VALD + c] = __float2bfloat16(val - __bfloat162float(hv));
    }
}

// ---------------- launch ----------------
extern "C" void kernel_launch(void* const* d_in, const int* in_sizes, int n_in,
                              void* d_out, int out_size) {
    const float* x       = (const float*)d_in[0];
    const float* W_qkvz  = (const float*)d_in[1];
    const float* W_ba    = (const float*)d_in[2];
    const float* conv_w  = (const float*)d_in[3];
    const float* dt_bias = (const float*)d_in[4];
    const float* A_log   = (const float*)d_in[5];
    const float* norm_w  = (const float*)d_in[6];
    const float* W_out   = (const float*)d_in[7];
    float* out = (float*)d_out;

    float *p_qkvz, *p_ba, *p_conv, *p_qn, *p_kn, *p_beta, *p_g, *p_core;
    __nv_bfloat16 *p_xhi, *p_xlo, *p_w1hi, *p_w1lo, *p_w2hi, *p_w2lo, *p_ghi, *p_glo;
    cudaGetSymbolAddress((void**)&p_qkvz,  g_qkvz);
    cudaGetSymbolAddress((void**)&p_ba,    g_ba);
    cudaGetSymbolAddress((void**)&p_conv,  g_conv);
    cudaGetSymbolAddress((void**)&p_qn,    g_qn);
    cudaGetSymbolAddress((void**)&p_kn,    g_kn);
    cudaGetSymbolAddress((void**)&p_beta,  g_beta);
    cudaGetSymbolAddress((void**)&p_g,     g_gdec);
    cudaGetSymbolAddress((void**)&p_core,  g_core);
    cudaGetSymbolAddress((void**)&p_xhi,  g_xhi);
    cudaGetSymbolAddress((void**)&p_xlo,  g_xlo);
    cudaGetSymbolAddress((void**)&p_w1hi, g_w1hi);
    cudaGetSymbolAddress((void**)&p_w1lo, g_w1lo);
    cudaGetSymbolAddress((void**)&p_w2hi, g_w2hi);
    cudaGetSymbolAddress((void**)&p_w2lo, g_w2lo);
    cudaGetSymbolAddress((void**)&p_ghi,  g_ghi);
    cudaGetSymbolAddress((void**)&p_glo,  g_glo);

    cudaFuncSetAttribute(gemm_bf16x3, cudaFuncAttributeMaxDynamicSharedMemorySize, GSMEM);

    // splits for GEMM operands
    split_bf16<<<(TOK * (size_t)HID) / 1024, 256>>>(x, p_xhi, p_xlo);
    split_bf16<<<((size_t)PQKVZ * HID) / 1024, 256>>>(W_qkvz, p_w1hi, p_w1lo);
    split_bf16<<<((size_t)HID * VALD) / 1024, 256>>>(W_out, p_w2hi, p_w2lo);

    // 1) qkvz = x @ W_qkvz^T  (mma.sync bf16x3 + ldmatrix)
    gemm_bf16x3<<<dim3(TOK / 128, PQKVZ / 128), 256, GSMEM>>>(
        p_xhi, p_xlo, p_w1hi, p_w1lo, p_qkvz, TOK, PQKVZ, HID);
    // 2) ba = x @ W_ba^T (SIMT, tiny)
    sgemm_nt<<<dim3(1, TOK / BM), 256>>>(x, W_ba, p_ba, TOK, 64, HID);
    // 3) conv + silu
    conv_silu_kernel<<<(TOK * (size_t)CONVD) / 256, 256>>>(p_qkvz, conv_w, p_conv);
    // 4) l2norm + gates
    prep_kernel<<<TOK, 512>>>(p_conv, p_ba, dt_bias, A_log, p_qn, p_kn, p_beta, p_g);
    // 5) delta-rule scan v3 (prefetched, 2 thr/col)
    scan_kernel<<<dim3(NV, BATCH), 256>>>(p_qn, p_kn, p_conv, p_beta, p_g, p_core);
    // 6) rmsnorm + gate -> bf16 hi/lo directly
    rmsnorm_gate_kernel<<<TOK, 256>>>(p_core, p_qkvz, norm_w, p_ghi, p_glo);
    // 7) out = gated @ W_out^T (mma.sync bf16x3 + ldmatrix)
    gemm_bf16x3<<<dim3(TOK / 128, HID / 128), 256, GSMEM>>>(
        p_ghi, p_glo, p_w2hi, p_w2lo, out, TOK, HID, VALD);
}

// round 7
// speedup vs baseline: 4.5832x; 1.4088x over previous
#include <cuda_runtime.h>
#include <cuda_bf16.h>
#include <cstdint>

// ---------------- model dims ----------------
#define BATCH 2
#define SEQ   2048
#define TOK   (BATCH*SEQ)        // 4096
#define HID   2048
#define NK    16
#define NV    32
#define DK    128
#define DV    128
#define KEYD  2048               // NK*DK
#define VALD  4096               // NV*DV
#define CONVD 8192               // 2*KEYD + VALD
#define PQKVZ 12288              // 2*KEYD + 2*VALD
#define EPSF  1e-6f

// ---------------- scratch (device globals; no allocation) ----------------
__device__ float g_qkvz [(size_t)TOK * PQKVZ];
__device__ float g_ba   [(size_t)TOK * 64];
__device__ float g_conv [(size_t)TOK * CONVD];
__device__ float g_qn   [(size_t)TOK * KEYD];
__device__ float g_kn   [(size_t)TOK * KEYD];
__device__ float g_beta [(size_t)TOK * NV];
__device__ float g_gdec [(size_t)TOK * NV];
__device__ float g_core [(size_t)TOK * VALD];
// bf16 hi/lo split scratch
__device__ __nv_bfloat16 g_xhi [(size_t)TOK * HID];
__device__ __nv_bfloat16 g_xlo [(size_t)TOK * HID];
__device__ __nv_bfloat16 g_w1hi[(size_t)PQKVZ * HID];
__device__ __nv_bfloat16 g_w1lo[(size_t)PQKVZ * HID];
__device__ __nv_bfloat16 g_w2hi[(size_t)HID * VALD];
__device__ __nv_bfloat16 g_w2lo[(size_t)HID * VALD];
__device__ __nv_bfloat16 g_ghi [(size_t)TOK * VALD];
__device__ __nv_bfloat16 g_glo [(size_t)TOK * VALD];

// ---------------- helpers ----------------
__device__ __forceinline__ uint32_t smem_u32(const void* p) {
    uint32_t r;
    asm("{ .reg .u64 t; cvta.to.shared.u64 t, %1; cvt.u32.u64 %0, t; }" : "=r"(r) : "l"(p));
    return r;
}
__device__ __forceinline__ void cpasync16(uint32_t s, const void* g) {
    asm volatile("cp.async.cg.shared.global [%0], [%1], 16;" :: "r"(s), "l"(g));
}
__device__ __forceinline__ void cpasync4(uint32_t s, const void* g) {
    asm volatile("cp.async.ca.shared.global [%0], [%1], 4;" :: "r"(s), "l"(g));
}
__device__ __forceinline__ void ldmx4(uint32_t* r, uint32_t addr) {
    asm volatile("ldmatrix.sync.aligned.m8n8.x4.shared.b16 {%0,%1,%2,%3}, [%4];"
                 : "=r"(r[0]), "=r"(r[1]), "=r"(r[2]), "=r"(r[3]) : "r"(addr));
}
__device__ __forceinline__ void mma16816(float* c, const uint32_t* a, const uint32_t* b) {
    asm volatile(
        "mma.sync.aligned.m16n8k16.row.col.f32.bf16.bf16.f32 "
        "{%0,%1,%2,%3}, {%4,%5,%6,%7}, {%8,%9}, {%0,%1,%2,%3};"
        : "+f"(c[0]), "+f"(c[1]), "+f"(c[2]), "+f"(c[3])
        : "r"(a[0]), "r"(a[1]), "r"(a[2]), "r"(a[3]), "r"(b[0]), "r"(b[1]));
}
// f32x2 packed math
__device__ __forceinline__ unsigned long long pk2(float a, float b) {
    unsigned long long r; asm("mov.b64 %0, {%1, %2};" : "=l"(r) : "f"(a), "f"(b)); return r;
}
__device__ __forceinline__ unsigned long long fma2(unsigned long long a, unsigned long long b, unsigned long long c) {
    unsigned long long d; asm("fma.rn.f32x2 %0, %1, %2, %3;" : "=l"(d) : "l"(a), "l"(b), "l"(c)); return d;
}
__device__ __forceinline__ unsigned long long mul2(unsigned long long a, unsigned long long b) {
    unsigned long long d; asm("mul.rn.f32x2 %0, %1, %2;" : "=l"(d) : "l"(a), "l"(b)); return d;
}
__device__ __forceinline__ float hadd2(unsigned long long v) {
    float a, b; asm("mov.b64 {%0, %1}, %2;" : "=f"(a), "=f"(b) : "l"(v)); return a + b;
}

// ---------------- split fp32 -> bf16 hi/lo ----------------
__global__ __launch_bounds__(256) void split_bf16(const float* __restrict__ src,
                                                  __nv_bfloat16* __restrict__ hi,
                                                  __nv_bfloat16* __restrict__ lo) {
    size_t i = ((size_t)blockIdx.x * blockDim.x + threadIdx.x) * 4;
    float4 v = *(const float4*)(src + i);
    __nv_bfloat16 h0 = __float2bfloat16(v.x), h1 = __float2bfloat16(v.y);
    __nv_bfloat16 h2 = __float2bfloat16(v.z), h3 = __float2bfloat16(v.w);
    __nv_bfloat16 l0 = __float2bfloat16(v.x - __bfloat162float(h0));
    __nv_bfloat16 l1 = __float2bfloat16(v.y - __bfloat162float(h1));
    __nv_bfloat16 l2 = __float2bfloat16(v.z - __bfloat162float(h2));
    __nv_bfloat16 l3 = __float2bfloat16(v.w - __bfloat162float(h3));
    __nv_bfloat162* hp = (__nv_bfloat162*)(hi + i);
    __nv_bfloat162* lp = (__nv_bfloat162*)(lo + i);
    hp[0] = __nv_bfloat162(h0, h1); hp[1] = __nv_bfloat162(h2, h3);
    lp[0] = __nv_bfloat162(l0, l1); lp[1] = __nv_bfloat162(l2, l3);
}

// ---------------- mma.sync bf16x3 GEMM (NT): C[m,n] = sum_k A[m,k]*B[n,k] ----------------
#define TSTRIDE 80
#define TILE_B  (128 * TSTRIDE)
#define STAGE_B (4 * TILE_B)
#define GSMEM   (2 * STAGE_B)

__global__ __launch_bounds__(256, 2)
void gemm_bf16x3(const __nv_bfloat16* __restrict__ Ah, const __nv_bfloat16* __restrict__ Al,
                 const __nv_bfloat16* __restrict__ Bh, const __nv_bfloat16* __restrict__ Bl,
                 float* __restrict__ C, int M, int N, int K) {
    extern __shared__ char sm[];
    const uint32_t sb = smem_u32(sm);
    const int tid = threadIdx.x;
    const int lane = tid & 31, wid = tid >> 5;
    const int bm = blockIdx.x * 128, bn = blockIdx.y * 128;
    const int wm = (wid & 1) * 64, wn = (wid >> 1) * 32;
    const int grp = lane >> 2, qid = lane & 3;

    const uint32_t a_row = (uint32_t)(lane & 15);
    const uint32_t a_c16 = (uint32_t)((lane >> 4) * 16);
    const uint32_t b_row = (uint32_t)((lane & 7) + ((lane >> 4) & 1) * 8);
    const uint32_t b_c16 = (uint32_t)(((lane >> 3) & 1) * 16);

    float c[4][4][4];
    #pragma unroll
    for (int i = 0; i < 4; i++)
        #pragma unroll
        for (int j = 0; j < 4; j++)
            #pragma unroll
            for (int r = 0; r < 4; r++) c[i][j][r] = 0.f;

    const int niter = K >> 5;

    auto issue = [&](int kblk, int buf) {
        const int k0 = kblk * 32;
        #pragma unroll
        for (int i = 0; i < 2; i++) {
            int chunk = tid + i * 256;
            int row = chunk >> 2, c16 = chunk & 3;
            size_t ga = (size_t)(bm + row) * K + k0 + c16 * 8;
            size_t gb = (size_t)(bn + row) * K + k0 + c16 * 8;
            uint32_t so = sb + buf * STAGE_B + row * TSTRIDE + c16 * 16;
            cpasync16(so,              Ah + ga);
            cpasync16(so + TILE_B,     Al + ga);
            cpasync16(so + 2 * TILE_B, Bh + gb);
            cpasync16(so + 3 * TILE_B, Bl + gb);
        }
    };

    issue(0, 0);
    asm volatile("cp.async.commit_group;" ::: "memory");
    issue(1, 1);
    asm volatile("cp.async.commit_group;" ::: "memory");

    for (int it = 0; it < niter; it++) {
        asm volatile("cp.async.wait_group 1;" ::: "memory");
        __syncthreads();
        const int buf = it & 1;
        const uint32_t base = sb + buf * STAGE_B;

        #pragma unroll
        for (int ks = 0; ks < 2; ks++) {
            const uint32_t koff = ks * 32;
            const uint32_t abase = base + (uint32_t)(wm + a_row) * TSTRIDE + koff + a_c16;
            const uint32_t bbase = base + 2 * TILE_B + (uint32_t)(wn + b_row) * TSTRIDE + koff + b_c16;
            uint32_t ah[4][4], bh[2][4];
            #pragma unroll
            for (int i = 0; i < 4; i++) ldmx4(ah[i], abase + (uint32_t)(i * 16) * TSTRIDE);
            #pragma unroll
            for (int J = 0; J < 2; J++) ldmx4(bh[J], bbase + (uint32_t)(J * 16) * TSTRIDE);
            // phase 1: hh
            #pragma unroll
            for (int i = 0; i < 4; i++)
                #pragma unroll
                for (int j = 0; j < 4; j++) mma16816(c[i][j], ah[i], &bh[j >> 1][(j & 1) * 2]);
            // phase 2: lh
            {
                uint32_t al[4][4];
                #pragma unroll
                for (int i = 0; i < 4; i++) ldmx4(al[i], abase + TILE_B + (uint32_t)(i * 16) * TSTRIDE);
                #pragma unroll
                for (int i = 0; i < 4; i++)
                    #pragma unroll
                    for (int j = 0; j < 4; j++) mma16816(c[i][j], al[i], &bh[j >> 1][(j & 1) * 2]);
            }
            // phase 3: hl
            {
                uint32_t bl[2][4];
                #pragma unroll
                for (int J = 0; J < 2; J++) ldmx4(bl[J], bbase + TILE_B + (uint32_t)(J * 16) * TSTRIDE);
                #pragma unroll
                for (int i = 0; i < 4; i++)
                    #pragma unroll
                    for (int j = 0; j < 4; j++) mma16816(c[i][j], ah[i], &bl[j >> 1][(j & 1) * 2]);
            }
        }
        __syncthreads();
        if (it + 2 < niter) issue(it + 2, buf);
        asm volatile("cp.async.commit_group;" ::: "memory");
    }

    #pragma unroll
    for (int i = 0; i < 4; i++) {
        const int row0 = bm + wm + i * 16 + grp;
        #pragma unroll
        for (int j = 0; j < 4; j++) {
            const int col = bn + wn + j * 8 + qid * 2;
            float2 v01 = make_float2(c[i][j][0], c[i][j][1]);
            float2 v23 = make_float2(c[i][j][2], c[i][j][3]);
            *(float2*)(C + (size_t)row0 * N + col)       = v01;
            *(float2*)(C + (size_t)(row0 + 8) * N + col) = v23;
        }
    }
}

// ---------------- SIMT SGEMM (NT) for tiny ba GEMM ----------------
#define BM 128
#define BN 128
#define BKK 16
__global__ __launch_bounds__(256) void sgemm_nt(const float* __restrict__ A,
                                                const float* __restrict__ B,
                                                float* __restrict__ C,
                                                int M, int N, int K) {
    __shared__ float As[BKK][BM];
    __shared__ float Bs[BKK][BN];
    const int tid = threadIdx.x;
    const int bm = blockIdx.y * BM;
    const int bn = blockIdx.x * BN;
    const int tx = tid & 15;
    const int ty = tid >> 4;
    const int lrow = tid >> 2;
    const int lk4 = (tid & 3) * 4;

    float acc[8][8];
    #pragma unroll
    for (int i = 0; i < 8; i++)
        #pragma unroll
        for (int j = 0; j < 8; j++) acc[i][j] = 0.f;

    for (int k0 = 0; k0 < K; k0 += BKK) {
        #pragma unroll
        for (int it = 0; it < 2; it++) {
            int row = lrow + it * 64;
            float4 v = *(const float4*)(A + (size_t)(bm + row) * K + k0 + lk4);
            As[lk4 + 0][row] = v.x; As[lk4 + 1][row] = v.y;
            As[lk4 + 2][row] = v.z; As[lk4 + 3][row] = v.w;
        }
        #pragma unroll
        for (int it = 0; it < 2; it++) {
            int row = lrow + it * 64;
            int gn = bn + row;
            float4 v = make_float4(0.f, 0.f, 0.f, 0.f);
            if (gn < N) v = *(const float4*)(B + (size_t)gn * K + k0 + lk4);
            Bs[lk4 + 0][row] = v.x; Bs[lk4 + 1][row] = v.y;
            Bs[lk4 + 2][row] = v.z; Bs[lk4 + 3][row] = v.w;
        }
        __syncthreads();
        #pragma unroll
        for (int kk = 0; kk < BKK; kk++) {
            float ar[8], br[8];
            #pragma unroll
            for (int i = 0; i < 8; i++) ar[i] = As[kk][ty * 8 + i];
            #pragma unroll
            for (int j = 0; j < 8; j++) br[j] = Bs[kk][tx * 8 + j];
            #pragma unroll
            for (int i = 0; i < 8; i++)
                #pragma unroll
                for (int j = 0; j < 8; j++)
                    acc[i][j] = fmaf(ar[i], br[j], acc[i][j]);
        }
        __syncthreads();
    }
    #pragma unroll
    for (int i = 0; i < 8; i++) {
        int gm = bm + ty * 8 + i;
        #pragma unroll
        for (int j = 0; j < 8; j++) {
            int gn = bn + tx * 8 + j;
            if (gn < N) C[(size_t)gm * N + gn] = acc[i][j];
        }
    }
}

// ---------------- depthwise causal conv1d (K=4) + SiLU ----------------
__global__ void conv_silu_kernel(const float* __restrict__ qkvz,
                                 const float* __restrict__ cw,
                                 float* __restrict__ out) {
    size_t idx = (size_t)blockIdx.x * blockDim.x + threadIdx.x;
    int c = (int)(idx & (CONVD - 1));
    size_t t = idx >> 13;
    int s = (int)(t & (SEQ - 1));
    size_t b = t >> 11;
    const float* base = qkvz + (b * SEQ) * (size_t)PQKVZ + c;
    float w0 = cw[c * 4 + 0], w1 = cw[c * 4 + 1], w2 = cw[c * 4 + 2], w3 = cw[c * 4 + 3];
    float acc = w3 * base[(size_t)s * PQKVZ];
    if (s >= 1) acc = fmaf(w2, base[(size_t)(s - 1) * PQKVZ], acc);
    if (s >= 2) acc = fmaf(w1, base[(size_t)(s - 2) * PQKVZ], acc);
    if (s >= 3) acc = fmaf(w0, base[(size_t)(s - 3) * PQKVZ], acc);
    out[idx] = acc / (1.f + expf(-acc));
}

// ---------------- l2norm(q,k) + gates ----------------
__global__ __launch_bounds__(512) void prep_kernel(const float* __restrict__ conv,
                                                   const float* __restrict__ ba,
                                                   const float* __restrict__ dt_bias,
                                                   const float* __restrict__ A_log,
                                                   float* __restrict__ qn,
                                                   float* __restrict__ kn,
                                                   float* __restrict__ beta,
                                                   float* __restrict__ gdec) {
    size_t t = blockIdx.x;
    int w = threadIdx.x >> 5;
    int l = threadIdx.x & 31;
    const float* cq = conv + t * CONVD + w * DK;
    const float* ck = conv + t * CONVD + KEYD + w * DK;
    float qv[4], kv[4];
    float sq = 0.f, sk = 0.f;
    #pragma unroll
    for (int i = 0; i < 4; i++) {
        qv[i] = cq[l + 32 * i]; sq = fmaf(qv[i], qv[i], sq);
        kv[i] = ck[l + 32 * i]; sk = fmaf(kv[i], kv[i], sk);
    }
    #pragma unroll
    for (int o = 16; o; o >>= 1) {
        sq += __shfl_xor_sync(0xffffffffu, sq, o);
        sk += __shfl_xor_sync(0xffffffffu, sk, o);
    }
    float rq = rsqrtf(sq + EPSF), rk = rsqrtf(sk + EPSF);
    #pragma unroll
    for (int i = 0; i < 4; i++) {
        qn[(t * NK + w) * DK + l + 32 * i] = qv[i] * rq;
        kn[(t * NK + w) * DK + l + 32 * i] = kv[i] * rk;
    }
    if (threadIdx.x < NV) {
        int h = threadIdx.x;
        float bv = ba[t * 64 + h];
        float av = ba[t * 64 + NV + h];
        beta[t * NV + h] = 1.f / (1.f + expf(-bv));
        float xx = av + dt_bias[h];
        float sp = (xx > 20.f) ? xx : log1pf(expf(xx));
        gdec[t * NV + h] = expf(-expf(A_log[h]) * sp);
    }
}

// ---------------- gated delta-rule scan v4: block-staged cp.async pipeline ----------------
// 256 threads, 2 per DV column (DK split 64/64). T=8 steps staged per block,
// double-buffered; k/q rows padded (half1 at float-offset 68) for conflict-free LDS.
#define SCH   8
#define KROW  136   // 64 | 4 pad | 64 | 4 pad  (544 B, 16B-aligned)
__global__ __launch_bounds__(256) void scan_kernel(const float* __restrict__ qn,
                                                   const float* __restrict__ kn,
                                                   const float* __restrict__ conv,
                                                   const float* __restrict__ beta,
                                                   const float* __restrict__ gdec,
                                                   float* __restrict__ core) {
    const int h = blockIdx.x;       // value head
    const int b = blockIdx.y;
    const int nk = h >> 1;
    const int tid = threadIdx.x;
    const int col = tid >> 1;       // DV column 0..127
    const int half = tid & 1;       // DK half 0/1
    __shared__ float ksm[2][SCH][KROW];
    __shared__ float qsm[2][SCH][KROW];
    __shared__ float vsm[2][SCH][128];
    __shared__ float gsm[2][SCH], bsm[2][SCH];

    unsigned long long st[32];
    #pragma unroll
    for (int j = 0; j < 32; j++) st[j] = 0ull;

    const size_t tbase = (size_t)b * SEQ;
    const int stp = tid >> 5, ln = tid & 31;
    // dst float offset inside padded row for this loader lane (16B chunks)
    const int kqoff = (ln < 16) ? ln * 4 : 68 + (ln - 16) * 4;

    auto issue = [&](int blk, int buf) {
        const size_t t0 = tbase + (size_t)blk * SCH;
        cpasync16(smem_u32(&ksm[buf][stp][kqoff]), kn + ((t0 + stp) * NK + nk) * DK + ln * 4);
        cpasync16(smem_u32(&qsm[buf][stp][kqoff]), qn + ((t0 + stp) * NK + nk) * DK + ln * 4);
        cpasync16(smem_u32(&vsm[buf][stp][ln * 4]), conv + (t0 + stp) * CONVD + 2 * KEYD + h * DV + ln * 4);
        if (tid < SCH)
            cpasync4(smem_u32(&gsm[buf][tid]), gdec + (t0 + tid) * NV + h);
        else if (tid < 2 * SCH)
            cpasync4(smem_u32(&bsm[buf][tid - SCH]), beta + (t0 + tid - SCH) * NV + h);
    };

    issue(0, 0);
    asm volatile("cp.async.commit_group;" ::: "memory");
    issue(1, 1);
    asm volatile("cp.async.commit_group;" ::: "memory");

    const int nblk = SEQ / SCH;
    for (int blk = 0; blk < nblk; blk++) {
        const int buf = blk & 1;
        asm volatile("cp.async.wait_group 1;" ::: "memory");
        __syncthreads();

        #pragma unroll
        for (int i = 0; i < SCH; i++) {
            const ulonglong2* kk = (const ulonglong2*)&ksm[buf][i][half * 68];
            const ulonglong2* qq = (const ulonglong2*)&qsm[buf][i][half * 68];
            float vt = vsm[buf][i][col];
            float ge = gsm[buf][i];
            float bt = bsm[buf][i];

            unsigned long long a0 = 0ull, a1 = 0ull;
            #pragma unroll
            for (int j = 0; j < 16; j++) {
                ulonglong2 kj = kk[j];
                a0 = fma2(kj.x, st[2 * j + 0], a0);
                a1 = fma2(kj.y, st[2 * j + 1], a1);
            }
            float kvd = hadd2(a0) + hadd2(a1);
            kvd += __shfl_xor_sync(0xffffffffu, kvd, 1);
            float delta = bt * (vt - ge * kvd);
            unsigned long long ge2 = pk2(ge, ge);
            unsigned long long d2 = pk2(delta, delta);

            unsigned long long o0 = 0ull, o1 = 0ull;
            #pragma unroll
            for (int j = 0; j < 16; j++) {
                ulonglong2 kj = kk[j], qj = qq[j];
                st[2 * j + 0] = fma2(ge2, st[2 * j + 0], mul2(kj.x, d2));
                o0 = fma2(qj.x, st[2 * j + 0], o0);
                st[2 * j + 1] = fma2(ge2, st[2 * j + 1], mul2(kj.y, d2));
                o1 = fma2(qj.y, st[2 * j + 1], o1);
            }
            float o = hadd2(o0) + hadd2(o1);
            o += __shfl_xor_sync(0xffffffffu, o, 1);
            if (half == 0)
                core[(tbase + (size_t)blk * SCH + i) * VALD + h * DV + col] = o;
        }

        __syncthreads();
        if (blk + 2 < nblk) issue(blk + 2, buf);
        asm volatile("cp.async.commit_group;" ::: "memory");
    }
}

// ---------------- RMSNorm(1+w) + silu(z) gate -> bf16 hi/lo ----------------
__global__ __launch_bounds__(256) void rmsnorm_gate_kernel(const float* __restrict__ core,
                                                           const float* __restrict__ qkvz,
                                                           const float* __restrict__ norm_w,
                                                           __nv_bfloat16* __restrict__ ghi,
                                                           __nv_bfloat16* __restrict__ glo) {
    size_t t = blockIdx.x;
    __shared__ float red[8];
    __shared__ float s_scale;
    const float* row = core + t * VALD;
    const float* zrow = qkvz + t * PQKVZ + 2 * KEYD + VALD;
    float ss = 0.f;
    for (int c = threadIdx.x; c < VALD; c += 256) { float v = row[c]; ss = fmaf(v, v, ss); }
    #pragma unroll
    for (int o = 16; o; o >>= 1) ss += __shfl_xor_sync(0xffffffffu, ss, o);
    if ((threadIdx.x & 31) == 0) red[threadIdx.x >> 5] = ss;
    __syncthreads();
    if (threadIdx.x == 0) {
        float tot = 0.f;
        #pragma unroll
        for (int i = 0; i < 8; i++) tot += red[i];
        s_scale = rsqrtf(tot * (1.f / VALD) + EPSF);
    }
    __syncthreads();
    float sc = s_scale;
    for (int c = threadIdx.x; c < VALD; c += 256) {
        float z = zrow[c];
        float sz = z / (1.f + expf(-z));
        float val = row[c] * sc * (1.f + norm_w[c]) * sz;
        __nv_bfloat16 hv = __float2bfloat16(val);
        ghi[t * VALD + c] = hv;
        glo[t * VALD + c] = __float2bfloat16(val - __bfloat162float(hv));
    }
}

// ---------------- launch ----------------
extern "C" void kernel_launch(void* const* d_in, const int* in_sizes, int n_in,
                              void* d_out, int out_size) {
    const float* x       = (const float*)d_in[0];
    const float* W_qkvz  = (const float*)d_in[1];
    const float* W_ba    = (const float*)d_in[2];
    const float* conv_w  = (const float*)d_in[3];
    const float* dt_bias = (const float*)d_in[4];
    const float* A_log   = (const float*)d_in[5];
    const float* norm_w  = (const float*)d_in[6];
    const float* W_out   = (const float*)d_in[7];
    float* out = (float*)d_out;

    float *p_qkvz, *p_ba, *p_conv, *p_qn, *p_kn, *p_beta, *p_g, *p_core;
    __nv_bfloat16 *p_xhi, *p_xlo, *p_w1hi, *p_w1lo, *p_w2hi, *p_w2lo, *p_ghi, *p_glo;
    cudaGetSymbolAddress((void**)&p_qkvz,  g_qkvz);
    cudaGetSymbolAddress((void**)&p_ba,    g_ba);
    cudaGetSymbolAddress((void**)&p_conv,  g_conv);
    cudaGetSymbolAddress((void**)&p_qn,    g_qn);
    cudaGetSymbolAddress((void**)&p_kn,    g_kn);
    cudaGetSymbolAddress((void**)&p_beta,  g_beta);
    cudaGetSymbolAddress((void**)&p_g,     g_gdec);
    cudaGetSymbolAddress((void**)&p_core,  g_core);
    cudaGetSymbolAddress((void**)&p_xhi,  g_xhi);
    cudaGetSymbolAddress((void**)&p_xlo,  g_xlo);
    cudaGetSymbolAddress((void**)&p_w1hi, g_w1hi);
    cudaGetSymbolAddress((void**)&p_w1lo, g_w1lo);
    cudaGetSymbolAddress((void**)&p_w2hi, g_w2hi);
    cudaGetSymbolAddress((void**)&p_w2lo, g_w2lo);
    cudaGetSymbolAddress((void**)&p_ghi,  g_ghi);
    cudaGetSymbolAddress((void**)&p_glo,  g_glo);

    cudaFuncSetAttribute(gemm_bf16x3, cudaFuncAttributeMaxDynamicSharedMemorySize, GSMEM);

    // splits for GEMM operands
    split_bf16<<<(TOK * (size_t)HID) / 1024, 256>>>(x, p_xhi, p_xlo);
    split_bf16<<<((size_t)PQKVZ * HID) / 1024, 256>>>(W_qkvz, p_w1hi, p_w1lo);
    split_bf16<<<((size_t)HID * VALD) / 1024, 256>>>(W_out, p_w2hi, p_w2lo);

    // 1) qkvz = x @ W_qkvz^T  (mma.sync bf16x3 + ldmatrix)
    gemm_bf16x3<<<dim3(TOK / 128, PQKVZ / 128), 256, GSMEM>>>(
        p_xhi, p_xlo, p_w1hi, p_w1lo, p_qkvz, TOK, PQKVZ, HID);
    // 2) ba = x @ W_ba^T (SIMT, tiny)
    sgemm_nt<<<dim3(1, TOK / BM), 256>>>(x, W_ba, p_ba, TOK, 64, HID);
    // 3) conv + silu
    conv_silu_kernel<<<(TOK * (size_t)CONVD) / 256, 256>>>(p_qkvz, conv_w, p_conv);
    // 4) l2norm + gates
    prep_kernel<<<TOK, 512>>>(p_conv, p_ba, dt_bias, A_log, p_qn, p_kn, p_beta, p_g);
    // 5) delta-rule scan v4 (block-staged pipeline)
    scan_kernel<<<dim3(NV, BATCH), 256>>>(p_qn, p_kn, p_conv, p_beta, p_g, p_core);
    // 6) rmsnorm + gate -> bf16 hi/lo directly
    rmsnorm_gate_kernel<<<TOK, 256>>>(p_core, p_qkvz, norm_w, p_ghi, p_glo);
    // 7) out = gated @ W_out^T (mma.sync bf16x3 + ldmatrix)
    gemm_bf16x3<<<dim3(TOK / 128, HID / 128), 256, GSMEM>>>(
        p_ghi, p_glo, p_w2hi, p_w2lo, out, TOK, HID, VALD);
}

// round 8
// speedup vs baseline: 4.8788x; 1.0645x over previous
#include <cuda_runtime.h>
#include <cuda_bf16.h>
#include <cstdint>

// ---------------- model dims ----------------
#define BATCH 2
#define SEQ   2048
#define TOK   (BATCH*SEQ)        // 4096
#define HID   2048
#define NK    16
#define NV    32
#define DK    128
#define DV    128
#define KEYD  2048               // NK*DK
#define VALD  4096               // NV*DV
#define CONVD 8192               // 2*KEYD + VALD
#define PQKVZ 12288              // 2*KEYD + 2*VALD
#define EPSF  1e-6f

// ---------------- scratch (device globals; no allocation) ----------------
__device__ float g_qkvz [(size_t)TOK * PQKVZ];
__device__ float g_ba   [(size_t)TOK * 64];
__device__ float g_conv [(size_t)TOK * CONVD];
__device__ float g_qn   [(size_t)TOK * KEYD];
__device__ float g_kn   [(size_t)TOK * KEYD];
__device__ float g_beta [(size_t)TOK * NV];
__device__ float g_gdec [(size_t)TOK * NV];
__device__ float g_core [(size_t)TOK * VALD];
// bf16 hi/lo split scratch
__device__ __nv_bfloat16 g_xhi [(size_t)TOK * HID];
__device__ __nv_bfloat16 g_xlo [(size_t)TOK * HID];
__device__ __nv_bfloat16 g_w1hi[(size_t)PQKVZ * HID];
__device__ __nv_bfloat16 g_w1lo[(size_t)PQKVZ * HID];
__device__ __nv_bfloat16 g_w2hi[(size_t)HID * VALD];
__device__ __nv_bfloat16 g_w2lo[(size_t)HID * VALD];
__device__ __nv_bfloat16 g_ghi [(size_t)TOK * VALD];
__device__ __nv_bfloat16 g_glo [(size_t)TOK * VALD];

// ---------------- helpers ----------------
__device__ __forceinline__ uint32_t smem_u32(const void* p) {
    uint32_t r;
    asm("{ .reg .u64 t; cvta.to.shared.u64 t, %1; cvt.u32.u64 %0, t; }" : "=r"(r) : "l"(p));
    return r;
}
__device__ __forceinline__ void cpasync16(uint32_t s, const void* g) {
    asm volatile("cp.async.cg.shared.global [%0], [%1], 16;" :: "r"(s), "l"(g));
}
__device__ __forceinline__ void cpasync4(uint32_t s, const void* g) {
    asm volatile("cp.async.ca.shared.global [%0], [%1], 4;" :: "r"(s), "l"(g));
}
__device__ __forceinline__ void ldmx4(uint32_t* r, uint32_t addr) {
    asm volatile("ldmatrix.sync.aligned.m8n8.x4.shared.b16 {%0,%1,%2,%3}, [%4];"
                 : "=r"(r[0]), "=r"(r[1]), "=r"(r[2]), "=r"(r[3]) : "r"(addr));
}
__device__ __forceinline__ void mma16816(float* c, const uint32_t* a, const uint32_t* b) {
    asm volatile(
        "mma.sync.aligned.m16n8k16.row.col.f32.bf16.bf16.f32 "
        "{%0,%1,%2,%3}, {%4,%5,%6,%7}, {%8,%9}, {%0,%1,%2,%3};"
        : "+f"(c[0]), "+f"(c[1]), "+f"(c[2]), "+f"(c[3])
        : "r"(a[0]), "r"(a[1]), "r"(a[2]), "r"(a[3]), "r"(b[0]), "r"(b[1]));
}
// f32x2 packed math
__device__ __forceinline__ unsigned long long pk2(float a, float b) {
    unsigned long long r; asm("mov.b64 %0, {%1, %2};" : "=l"(r) : "f"(a), "f"(b)); return r;
}
__device__ __forceinline__ unsigned long long fma2(unsigned long long a, unsigned long long b, unsigned long long c) {
    unsigned long long d; asm("fma.rn.f32x2 %0, %1, %2, %3;" : "=l"(d) : "l"(a), "l"(b), "l"(c)); return d;
}
__device__ __forceinline__ unsigned long long mul2(unsigned long long a, unsigned long long b) {
    unsigned long long d; asm("mul.rn.f32x2 %0, %1, %2;" : "=l"(d) : "l"(a), "l"(b)); return d;
}
__device__ __forceinline__ float hadd2(unsigned long long v) {
    float a, b; asm("mov.b64 {%0, %1}, %2;" : "=f"(a), "=f"(b) : "l"(v)); return a + b;
}

// ---------------- split fp32 -> bf16 hi/lo ----------------
__global__ __launch_bounds__(256) void split_bf16(const float* __restrict__ src,
                                                  __nv_bfloat16* __restrict__ hi,
                                                  __nv_bfloat16* __restrict__ lo) {
    size_t i = ((size_t)blockIdx.x * blockDim.x + threadIdx.x) * 4;
    float4 v = *(const float4*)(src + i);
    __nv_bfloat16 h0 = __float2bfloat16(v.x), h1 = __float2bfloat16(v.y);
    __nv_bfloat16 h2 = __float2bfloat16(v.z), h3 = __float2bfloat16(v.w);
    __nv_bfloat16 l0 = __float2bfloat16(v.x - __bfloat162float(h0));
    __nv_bfloat16 l1 = __float2bfloat16(v.y - __bfloat162float(h1));
    __nv_bfloat16 l2 = __float2bfloat16(v.z - __bfloat162float(h2));
    __nv_bfloat16 l3 = __float2bfloat16(v.w - __bfloat162float(h3));
    __nv_bfloat162* hp = (__nv_bfloat162*)(hi + i);
    __nv_bfloat162* lp = (__nv_bfloat162*)(lo + i);
    hp[0] = __nv_bfloat162(h0, h1); hp[1] = __nv_bfloat162(h2, h3);
    lp[0] = __nv_bfloat162(l0, l1); lp[1] = __nv_bfloat162(l2, l3);
}

// ---------------- mma.sync bf16x3 GEMM (NT): C[m,n] = sum_k A[m,k]*B[n,k] ----------------
#define TSTRIDE 80
#define TILE_B  (128 * TSTRIDE)
#define STAGE_B (4 * TILE_B)
#define GSMEM   (2 * STAGE_B)

__global__ __launch_bounds__(256, 2)
void gemm_bf16x3(const __nv_bfloat16* __restrict__ Ah, const __nv_bfloat16* __restrict__ Al,
                 const __nv_bfloat16* __restrict__ Bh, const __nv_bfloat16* __restrict__ Bl,
                 float* __restrict__ C, int M, int N, int K) {
    extern __shared__ char sm[];
    const uint32_t sb = smem_u32(sm);
    const int tid = threadIdx.x;
    const int lane = tid & 31, wid = tid >> 5;
    const int bm = blockIdx.x * 128, bn = blockIdx.y * 128;
    const int wm = (wid & 1) * 64, wn = (wid >> 1) * 32;
    const int grp = lane >> 2, qid = lane & 3;

    const uint32_t a_row = (uint32_t)(lane & 15);
    const uint32_t a_c16 = (uint32_t)((lane >> 4) * 16);
    const uint32_t b_row = (uint32_t)((lane & 7) + ((lane >> 4) & 1) * 8);
    const uint32_t b_c16 = (uint32_t)(((lane >> 3) & 1) * 16);

    float c[4][4][4];
    #pragma unroll
    for (int i = 0; i < 4; i++)
        #pragma unroll
        for (int j = 0; j < 4; j++)
            #pragma unroll
            for (int r = 0; r < 4; r++) c[i][j][r] = 0.f;

    const int niter = K >> 5;

    auto issue = [&](int kblk, int buf) {
        const int k0 = kblk * 32;
        #pragma unroll
        for (int i = 0; i < 2; i++) {
            int chunk = tid + i * 256;
            int row = chunk >> 2, c16 = chunk & 3;
            size_t ga = (size_t)(bm + row) * K + k0 + c16 * 8;
            size_t gb = (size_t)(bn + row) * K + k0 + c16 * 8;
            uint32_t so = sb + buf * STAGE_B + row * TSTRIDE + c16 * 16;
            cpasync16(so,              Ah + ga);
            cpasync16(so + TILE_B,     Al + ga);
            cpasync16(so + 2 * TILE_B, Bh + gb);
            cpasync16(so + 3 * TILE_B, Bl + gb);
        }
    };

    issue(0, 0);
    asm volatile("cp.async.commit_group;" ::: "memory");
    issue(1, 1);
    asm volatile("cp.async.commit_group;" ::: "memory");

    for (int it = 0; it < niter; it++) {
        asm volatile("cp.async.wait_group 1;" ::: "memory");
        __syncthreads();
        const int buf = it & 1;
        const uint32_t base = sb + buf * STAGE_B;

        #pragma unroll
        for (int ks = 0; ks < 2; ks++) {
            const uint32_t koff = ks * 32;
            const uint32_t abase = base + (uint32_t)(wm + a_row) * TSTRIDE + koff + a_c16;
            const uint32_t bbase = base + 2 * TILE_B + (uint32_t)(wn + b_row) * TSTRIDE + koff + b_c16;
            uint32_t ah[4][4], bh[2][4];
            #pragma unroll
            for (int i = 0; i < 4; i++) ldmx4(ah[i], abase + (uint32_t)(i * 16) * TSTRIDE);
            #pragma unroll
            for (int J = 0; J < 2; J++) ldmx4(bh[J], bbase + (uint32_t)(J * 16) * TSTRIDE);
            // phase 1: hh
            #pragma unroll
            for (int i = 0; i < 4; i++)
                #pragma unroll
                for (int j = 0; j < 4; j++) mma16816(c[i][j], ah[i], &bh[j >> 1][(j & 1) * 2]);
            // phase 2: lh
            {
                uint32_t al[4][4];
                #pragma unroll
                for (int i = 0; i < 4; i++) ldmx4(al[i], abase + TILE_B + (uint32_t)(i * 16) * TSTRIDE);
                #pragma unroll
                for (int i = 0; i < 4; i++)
                    #pragma unroll
                    for (int j = 0; j < 4; j++) mma16816(c[i][j], al[i], &bh[j >> 1][(j & 1) * 2]);
            }
            // phase 3: hl
            {
                uint32_t bl[2][4];
                #pragma unroll
                for (int J = 0; J < 2; J++) ldmx4(bl[J], bbase + TILE_B + (uint32_t)(J * 16) * TSTRIDE);
                #pragma unroll
                for (int i = 0; i < 4; i++)
                    #pragma unroll
                    for (int j = 0; j < 4; j++) mma16816(c[i][j], ah[i], &bl[j >> 1][(j & 1) * 2]);
            }
        }
        __syncthreads();
        if (it + 2 < niter) issue(it + 2, buf);
        asm volatile("cp.async.commit_group;" ::: "memory");
    }

    #pragma unroll
    for (int i = 0; i < 4; i++) {
        const int row0 = bm + wm + i * 16 + grp;
        #pragma unroll
        for (int j = 0; j < 4; j++) {
            const int col = bn + wn + j * 8 + qid * 2;
            float2 v01 = make_float2(c[i][j][0], c[i][j][1]);
            float2 v23 = make_float2(c[i][j][2], c[i][j][3]);
            *(float2*)(C + (size_t)row0 * N + col)       = v01;
            *(float2*)(C + (size_t)(row0 + 8) * N + col) = v23;
        }
    }
}

// ---------------- SIMT SGEMM (NT) for tiny ba GEMM ----------------
#define BM 128
#define BN 128
#define BKK 16
__global__ __launch_bounds__(256) void sgemm_nt(const float* __restrict__ A,
                                                const float* __restrict__ B,
                                                float* __restrict__ C,
                                                int M, int N, int K) {
    __shared__ float As[BKK][BM];
    __shared__ float Bs[BKK][BN];
    const int tid = threadIdx.x;
    const int bm = blockIdx.y * BM;
    const int bn = blockIdx.x * BN;
    const int tx = tid & 15;
    const int ty = tid >> 4;
    const int lrow = tid >> 2;
    const int lk4 = (tid & 3) * 4;

    float acc[8][8];
    #pragma unroll
    for (int i = 0; i < 8; i++)
        #pragma unroll
        for (int j = 0; j < 8; j++) acc[i][j] = 0.f;

    for (int k0 = 0; k0 < K; k0 += BKK) {
        #pragma unroll
        for (int it = 0; it < 2; it++) {
            int row = lrow + it * 64;
            float4 v = *(const float4*)(A + (size_t)(bm + row) * K + k0 + lk4);
            As[lk4 + 0][row] = v.x; As[lk4 + 1][row] = v.y;
            As[lk4 + 2][row] = v.z; As[lk4 + 3][row] = v.w;
        }
        #pragma unroll
        for (int it = 0; it < 2; it++) {
            int row = lrow + it * 64;
            int gn = bn + row;
            float4 v = make_float4(0.f, 0.f, 0.f, 0.f);
            if (gn < N) v = *(const float4*)(B + (size_t)gn * K + k0 + lk4);
            Bs[lk4 + 0][row] = v.x; Bs[lk4 + 1][row] = v.y;
            Bs[lk4 + 2][row] = v.z; Bs[lk4 + 3][row] = v.w;
        }
        __syncthreads();
        #pragma unroll
        for (int kk = 0; kk < BKK; kk++) {
            float ar[8], br[8];
            #pragma unroll
            for (int i = 0; i < 8; i++) ar[i] = As[kk][ty * 8 + i];
            #pragma unroll
            for (int j = 0; j < 8; j++) br[j] = Bs[kk][tx * 8 + j];
            #pragma unroll
            for (int i = 0; i < 8; i++)
                #pragma unroll
                for (int j = 0; j < 8; j++)
                    acc[i][j] = fmaf(ar[i], br[j], acc[i][j]);
        }
        __syncthreads();
    }
    #pragma unroll
    for (int i = 0; i < 8; i++) {
        int gm = bm + ty * 8 + i;
        #pragma unroll
        for (int j = 0; j < 8; j++) {
            int gn = bn + tx * 8 + j;
            if (gn < N) C[(size_t)gm * N + gn] = acc[i][j];
        }
    }
}

// ---------------- depthwise causal conv1d (K=4) + SiLU ----------------
__global__ void conv_silu_kernel(const float* __restrict__ qkvz,
                                 const float* __restrict__ cw,
                                 float* __restrict__ out) {
    size_t idx = (size_t)blockIdx.x * blockDim.x + threadIdx.x;
    int c = (int)(idx & (CONVD - 1));
    size_t t = idx >> 13;
    int s = (int)(t & (SEQ - 1));
    size_t b = t >> 11;
    const float* base = qkvz + (b * SEQ) * (size_t)PQKVZ + c;
    float w0 = cw[c * 4 + 0], w1 = cw[c * 4 + 1], w2 = cw[c * 4 + 2], w3 = cw[c * 4 + 3];
    float acc = w3 * base[(size_t)s * PQKVZ];
    if (s >= 1) acc = fmaf(w2, base[(size_t)(s - 1) * PQKVZ], acc);
    if (s >= 2) acc = fmaf(w1, base[(size_t)(s - 2) * PQKVZ], acc);
    if (s >= 3) acc = fmaf(w0, base[(size_t)(s - 3) * PQKVZ], acc);
    out[idx] = acc / (1.f + expf(-acc));
}

// ---------------- l2norm(q,k) + gates ----------------
__global__ __launch_bounds__(512) void prep_kernel(const float* __restrict__ conv,
                                                   const float* __restrict__ ba,
                                                   const float* __restrict__ dt_bias,
                                                   const float* __restrict__ A_log,
                                                   float* __restrict__ qn,
                                                   float* __restrict__ kn,
                                                   float* __restrict__ beta,
                                                   float* __restrict__ gdec) {
    size_t t = blockIdx.x;
    int w = threadIdx.x >> 5;
    int l = threadIdx.x & 31;
    const float* cq = conv + t * CONVD + w * DK;
    const float* ck = conv + t * CONVD + KEYD + w * DK;
    float qv[4], kv[4];
    float sq = 0.f, sk = 0.f;
    #pragma unroll
    for (int i = 0; i < 4; i++) {
        qv[i] = cq[l + 32 * i]; sq = fmaf(qv[i], qv[i], sq);
        kv[i] = ck[l + 32 * i]; sk = fmaf(kv[i], kv[i], sk);
    }
    #pragma unroll
    for (int o = 16; o; o >>= 1) {
        sq += __shfl_xor_sync(0xffffffffu, sq, o);
        sk += __shfl_xor_sync(0xffffffffu, sk, o);
    }
    float rq = rsqrtf(sq + EPSF), rk = rsqrtf(sk + EPSF);
    #pragma unroll
    for (int i = 0; i < 4; i++) {
        qn[(t * NK + w) * DK + l + 32 * i] = qv[i] * rq;
        kn[(t * NK + w) * DK + l + 32 * i] = kv[i] * rk;
    }
    if (threadIdx.x < NV) {
        int h = threadIdx.x;
        float bv = ba[t * 64 + h];
        float av = ba[t * 64 + NV + h];
        beta[t * NV + h] = 1.f / (1.f + expf(-bv));
        float xx = av + dt_bias[h];
        float sp = (xx > 20.f) ? xx : log1pf(expf(xx));
        gdec[t * NV + h] = expf(-expf(A_log[h]) * sp);
    }
}

// ---------------- gated delta-rule scan v5 ----------------
// Grid (NV, 2, BATCH) = 128 CTAs; 256 threads: 4 per DV column (DK quarters of 32),
// each CTA owns 64 DV columns. Block-staged cp.async pipeline (SCH=8, double buffer).
// k/q rows stored with quarter q at float offset q*36 (conflict-free 4-addr broadcast).
#define SCH   8
#define KROW  144   // 4 quarters * 36 floats
__global__ __launch_bounds__(256) void scan_kernel(const float* __restrict__ qn,
                                                   const float* __restrict__ kn,
                                                   const float* __restrict__ conv,
                                                   const float* __restrict__ beta,
                                                   const float* __restrict__ gdec,
                                                   float* __restrict__ core) {
    const int h = blockIdx.x;        // value head
    const int dv0 = blockIdx.y * 64; // DV half
    const int b = blockIdx.z;
    const int nk = h >> 1;
    const int tid = threadIdx.x;
    const int col = tid >> 2;        // local DV col 0..63
    const int quarter = tid & 3;     // DK quarter
    __shared__ float ksm[2][SCH][KROW];
    __shared__ float qsm[2][SCH][KROW];
    __shared__ float vsm[2][SCH][64];
    __shared__ float gsm[2][SCH], bsm[2][SCH];

    unsigned long long st[16];       // 32 floats of state (this quarter x this col)
    #pragma unroll
    for (int j = 0; j < 16; j++) st[j] = 0ull;

    const size_t tbase = (size_t)b * SEQ;
    const int krow_t = tid >> 5, kln = tid & 31;
    const int kqoff = (kln >> 3) * 36 + (kln & 7) * 4;   // quarter-padded dst offset

    auto issue = [&](int blk, int buf) {
        const size_t t0 = tbase + (size_t)blk * SCH;
        cpasync16(smem_u32(&ksm[buf][krow_t][kqoff]), kn + ((t0 + krow_t) * NK + nk) * DK + kln * 4);
        cpasync16(smem_u32(&qsm[buf][krow_t][kqoff]), qn + ((t0 + krow_t) * NK + nk) * DK + kln * 4);
        if (tid < 128) {
            int vr = tid >> 4, vc = (tid & 15) * 4;
            cpasync16(smem_u32(&vsm[buf][vr][vc]),
                      conv + (t0 + vr) * CONVD + 2 * KEYD + h * DV + dv0 + vc);
        } else if (tid < 128 + SCH) {
            cpasync4(smem_u32(&gsm[buf][tid - 128]), gdec + (t0 + tid - 128) * NV + h);
        } else if (tid < 128 + 2 * SCH) {
            cpasync4(smem_u32(&bsm[buf][tid - 128 - SCH]), beta + (t0 + tid - 128 - SCH) * NV + h);
        }
    };

    issue(0, 0);
    asm volatile("cp.async.commit_group;" ::: "memory");
    issue(1, 1);
    asm volatile("cp.async.commit_group;" ::: "memory");

    const int nblk = SEQ / SCH;
    for (int blk = 0; blk < nblk; blk++) {
        const int buf = blk & 1;
        asm volatile("cp.async.wait_group 1;" ::: "memory");
        __syncthreads();

        #pragma unroll
        for (int i = 0; i < SCH; i++) {
            const ulonglong2* kk = (const ulonglong2*)&ksm[buf][i][quarter * 36];
            const ulonglong2* qq = (const ulonglong2*)&qsm[buf][i][quarter * 36];
            float vt = vsm[buf][i][col];
            float ge = gsm[buf][i];
            float bt = bsm[buf][i];

            unsigned long long a0 = 0ull, a1 = 0ull;
            #pragma unroll
            for (int j = 0; j < 8; j++) {
                ulonglong2 kj = kk[j];
                a0 = fma2(kj.x, st[2 * j + 0], a0);
                a1 = fma2(kj.y, st[2 * j + 1], a1);
            }
            float kvd = hadd2(a0) + hadd2(a1);
            kvd += __shfl_xor_sync(0xffffffffu, kvd, 1);
            kvd += __shfl_xor_sync(0xffffffffu, kvd, 2);
            float delta = bt * (vt - ge * kvd);
            unsigned long long ge2 = pk2(ge, ge);
            unsigned long long d2 = pk2(delta, delta);

            unsigned long long o0 = 0ull, o1 = 0ull;
            #pragma unroll
            for (int j = 0; j < 8; j++) {
                ulonglong2 kj = kk[j], qj = qq[j];
                st[2 * j + 0] = fma2(ge2, st[2 * j + 0], mul2(kj.x, d2));
                o0 = fma2(qj.x, st[2 * j + 0], o0);
                st[2 * j + 1] = fma2(ge2, st[2 * j + 1], mul2(kj.y, d2));
                o1 = fma2(qj.y, st[2 * j + 1], o1);
            }
            float o = hadd2(o0) + hadd2(o1);
            o += __shfl_xor_sync(0xffffffffu, o, 1);
            o += __shfl_xor_sync(0xffffffffu, o, 2);
            if (quarter == 0)
                core[(tbase + (size_t)blk * SCH + i) * VALD + h * DV + dv0 + col] = o;
        }

        __syncthreads();
        if (blk + 2 < nblk) issue(blk + 2, buf);
        asm volatile("cp.async.commit_group;" ::: "memory");
    }
}

// ---------------- RMSNorm(1+w) + silu(z) gate -> bf16 hi/lo ----------------
__global__ __launch_bounds__(256) void rmsnorm_gate_kernel(const float* __restrict__ core,
                                                           const float* __restrict__ qkvz,
                                                           const float* __restrict__ norm_w,
                                                           __nv_bfloat16* __restrict__ ghi,
                                                           __nv_bfloat16* __restrict__ glo) {
    size_t t = blockIdx.x;
    __shared__ float red[8];
    __shared__ float s_scale;
    const float* row = core + t * VALD;
    const float* zrow = qkvz + t * PQKVZ + 2 * KEYD + VALD;
    float ss = 0.f;
    for (int c = threadIdx.x; c < VALD; c += 256) { float v = row[c]; ss = fmaf(v, v, ss); }
    #pragma unroll
    for (int o = 16; o; o >>= 1) ss += __shfl_xor_sync(0xffffffffu, ss, o);
    if ((threadIdx.x & 31) == 0) red[threadIdx.x >> 5] = ss;
    __syncthreads();
    if (threadIdx.x == 0) {
        float tot = 0.f;
        #pragma unroll
        for (int i = 0; i < 8; i++) tot += red[i];
        s_scale = rsqrtf(tot * (1.f / VALD) + EPSF);
    }
    __syncthreads();
    float sc = s_scale;
    for (int c = threadIdx.x; c < VALD; c += 256) {
        float z = zrow[c];
        float sz = z / (1.f + expf(-z));
        float val = row[c] * sc * (1.f + norm_w[c]) * sz;
        __nv_bfloat16 hv = __float2bfloat16(val);
        ghi[t * VALD + c] = hv;
        glo[t * VALD + c] = __float2bfloat16(val - __bfloat162float(hv));
    }
}

// ---------------- launch ----------------
extern "C" void kernel_launch(void* const* d_in, const int* in_sizes, int n_in,
                              void* d_out, int out_size) {
    const float* x       = (const float*)d_in[0];
    const float* W_qkvz  = (const float*)d_in[1];
    const float* W_ba    = (const float*)d_in[2];
    const float* conv_w  = (const float*)d_in[3];
    const float* dt_bias = (const float*)d_in[4];
    const float* A_log   = (const float*)d_in[5];
    const float* norm_w  = (const float*)d_in[6];
    const float* W_out   = (const float*)d_in[7];
    float* out = (float*)d_out;

    float *p_qkvz, *p_ba, *p_conv, *p_qn, *p_kn, *p_beta, *p_g, *p_core;
    __nv_bfloat16 *p_xhi, *p_xlo, *p_w1hi, *p_w1lo, *p_w2hi, *p_w2lo, *p_ghi, *p_glo;
    cudaGetSymbolAddress((void**)&p_qkvz,  g_qkvz);
    cudaGetSymbolAddress((void**)&p_ba,    g_ba);
    cudaGetSymbolAddress((void**)&p_conv,  g_conv);
    cudaGetSymbolAddress((void**)&p_qn,    g_qn);
    cudaGetSymbolAddress((void**)&p_kn,    g_kn);
    cudaGetSymbolAddress((void**)&p_beta,  g_beta);
    cudaGetSymbolAddress((void**)&p_g,     g_gdec);
    cudaGetSymbolAddress((void**)&p_core,  g_core);
    cudaGetSymbolAddress((void**)&p_xhi,  g_xhi);
    cudaGetSymbolAddress((void**)&p_xlo,  g_xlo);
    cudaGetSymbolAddress((void**)&p_w1hi, g_w1hi);
    cudaGetSymbolAddress((void**)&p_w1lo, g_w1lo);
    cudaGetSymbolAddress((void**)&p_w2hi, g_w2hi);
    cudaGetSymbolAddress((void**)&p_w2lo, g_w2lo);
    cudaGetSymbolAddress((void**)&p_ghi,  g_ghi);
    cudaGetSymbolAddress((void**)&p_glo,  g_glo);

    cudaFuncSetAttribute(gemm_bf16x3, cudaFuncAttributeMaxDynamicSharedMemorySize, GSMEM);

    // splits for GEMM operands
    split_bf16<<<(TOK * (size_t)HID) / 1024, 256>>>(x, p_xhi, p_xlo);
    split_bf16<<<((size_t)PQKVZ * HID) / 1024, 256>>>(W_qkvz, p_w1hi, p_w1lo);
    split_bf16<<<((size_t)HID * VALD) / 1024, 256>>>(W_out, p_w2hi, p_w2lo);

    // 1) qkvz = x @ W_qkvz^T  (mma.sync bf16x3 + ldmatrix)
    gemm_bf16x3<<<dim3(TOK / 128, PQKVZ / 128), 256, GSMEM>>>(
        p_xhi, p_xlo, p_w1hi, p_w1lo, p_qkvz, TOK, PQKVZ, HID);
    // 2) ba = x @ W_ba^T (SIMT, tiny)
    sgemm_nt<<<dim3(1, TOK / BM), 256>>>(x, W_ba, p_ba, TOK, 64, HID);
    // 3) conv + silu
    conv_silu_kernel<<<(TOK * (size_t)CONVD) / 256, 256>>>(p_qkvz, conv_w, p_conv);
    // 4) l2norm + gates
    prep_kernel<<<TOK, 512>>>(p_conv, p_ba, dt_bias, A_log, p_qn, p_kn, p_beta, p_g);
    // 5) delta-rule scan v5 (DV-split x2, 4 thr/col)
    scan_kernel<<<dim3(NV, 2, BATCH), 256>>>(p_qn, p_kn, p_conv, p_beta, p_g, p_core);
    // 6) rmsnorm + gate -> bf16 hi/lo directly
    rmsnorm_gate_kernel<<<TOK, 256>>>(p_core, p_qkvz, norm_w, p_ghi, p_glo);
    // 7) out = gated @ W_out^T (mma.sync bf16x3 + ldmatrix)
    gemm_bf16x3<<<dim3(TOK / 128, HID / 128), 256, GSMEM>>>(
        p_ghi, p_glo, p_w2hi, p_w2lo, out, TOK, HID, VALD);
}